// round 1
// baseline (speedup 1.0000x reference)
#include <cuda_runtime.h>
#include <cuda_bf16.h>
#include <math.h>
#include <stdint.h>

// Problem constants
#define TT   2048
#define DD   768
#define HH   12
#define DKK  64
#define FFF  2048
#define VV   50304
#define LL   12
#define KC   4
#define EPSF 1e-6f

// ---------------- scratch (__device__ globals; no allocation allowed) ----------------
__device__ float g_h[TT * DD];
__device__ float g_x[TT * DD];
__device__ float g_t0[TT * DD];
__device__ float g_t1[TT * DD];
__device__ float g_t2[TT * DD];
__device__ float g_q[TT * DD];
__device__ float g_k[TT * DD];
__device__ float g_v[TT * DD];
__device__ float g_o[TT * DD];
__device__ float g_beta[TT * HH];
__device__ float g_gate[TT * FFF];
__device__ float g_up[TT * FFF];
__device__ float g_nll[TT];
__device__ float g_msk[TT];
__device__ float g_logits_fb[(size_t)TT * VV];  // used only if harness wants loss-only output

// ---------------- kernels ----------------

__global__ void embed_k(const int* __restrict__ idx, const float* __restrict__ emb,
                        float* __restrict__ out) {
    int t = blockIdx.x;
    int row = idx[t];
    const float* src = emb + (size_t)row * DD;
    float* dst = out + (size_t)t * DD;
    for (int d = threadIdx.x; d < DD; d += blockDim.x) dst[d] = src[d];
}

// rmsnorm over n columns, one block per row
__global__ void rmsnorm_k(const float* __restrict__ in, const float* __restrict__ w,
                          float* __restrict__ out, int n) {
    int t = blockIdx.x;
    const float* r = in + (size_t)t * n;
    float* wr = out + (size_t)t * n;
    int tid = threadIdx.x;
    __shared__ float red[256];
    float s = 0.f;
    for (int i = tid; i < n; i += 256) { float vv = r[i]; s += vv * vv; }
    red[tid] = s; __syncthreads();
    for (int o = 128; o > 0; o >>= 1) { if (tid < o) red[tid] += red[tid + o]; __syncthreads(); }
    float rs = rsqrtf(red[0] / (float)n + EPSF);
    for (int i = tid; i < n; i += 256) wr[i] = r[i] * rs * w[i];
}

// C[M,N] = A[M,K] @ B[K,N]   (row-major, all dims divisible: M%128==0, N%64==0, K%16==0)
template <bool ADD>
__global__ __launch_bounds__(256) void sgemm_k(const float* __restrict__ A,
                                               const float* __restrict__ B,
                                               float* __restrict__ C,
                                               int M, int N, int Kd) {
    const int BM = 128, BN = 64, BK = 16;
    __shared__ float As[BM][BK + 1];
    __shared__ float Bs[BK][BN];
    int bm = blockIdx.y * BM, bn = blockIdx.x * BN;
    int tid = threadIdx.x;
    int tx = tid & 15, ty = tid >> 4;
    float acc[8][4];
#pragma unroll
    for (int i = 0; i < 8; i++)
#pragma unroll
        for (int j = 0; j < 4; j++) acc[i][j] = 0.f;

    const float* Ab = A + (size_t)bm * Kd;
    for (int k0 = 0; k0 < Kd; k0 += BK) {
#pragma unroll
        for (int i = 0; i < 8; i++) {
            int li = tid + i * 256;
            int r = li >> 4, c = li & 15;
            As[r][c] = Ab[(size_t)r * Kd + k0 + c];
        }
#pragma unroll
        for (int i = 0; i < 4; i++) {
            int li = tid + i * 256;
            int r = li >> 6, c = li & 63;
            Bs[r][c] = B[(size_t)(k0 + r) * N + bn + c];
        }
        __syncthreads();
#pragma unroll
        for (int kk = 0; kk < BK; kk++) {
            float a[8];
#pragma unroll
            for (int i = 0; i < 8; i++) a[i] = As[ty * 8 + i][kk];
            float4 bv = *reinterpret_cast<const float4*>(&Bs[kk][tx * 4]);
            float b[4] = {bv.x, bv.y, bv.z, bv.w};
#pragma unroll
            for (int i = 0; i < 8; i++)
#pragma unroll
                for (int j = 0; j < 4; j++) acc[i][j] += a[i] * b[j];
        }
        __syncthreads();
    }
#pragma unroll
    for (int i = 0; i < 8; i++) {
        size_t row = (size_t)(bm + ty * 8 + i);
#pragma unroll
        for (int j = 0; j < 4; j++) {
            size_t cidx = row * N + bn + tx * 4 + j;
            if (ADD) C[cidx] += acc[i][j]; else C[cidx] = acc[i][j];
        }
    }
}

// causal depthwise conv (K=4) + SiLU;  x:[T,D], w:[D,K]
__global__ void conv_silu_k(const float* __restrict__ x, const float* __restrict__ w,
                            float* __restrict__ out) {
    int i = blockIdx.x * blockDim.x + threadIdx.x;
    if (i >= TT * DD) return;
    int t = i / DD, d = i % DD;
    float acc = 0.f;
#pragma unroll
    for (int j = 0; j < KC; j++) {
        int tt = t - (KC - 1) + j;
        if (tt >= 0) acc += x[(size_t)tt * DD + d] * w[d * KC + j];
    }
    out[i] = acc / (1.f + expf(-acc));  // silu
}

// per-64-row norm. mode 0: l2norm (sum, no weight). mode 1: rmsnorm (mean) * w[64]
__global__ void headnorm_k(float* __restrict__ data, const float* __restrict__ w, int mode) {
    int gw = (blockIdx.x * blockDim.x + threadIdx.x) >> 5;
    int lane = threadIdx.x & 31;
    if (gw >= TT * HH) return;
    float* r = data + (size_t)gw * 64;   // [t][h*64] contiguous
    float a = r[lane], b = r[lane + 32];
    float s = a * a + b * b;
#pragma unroll
    for (int o = 16; o > 0; o >>= 1) s += __shfl_xor_sync(0xffffffffu, s, o);
    if (mode == 0) {
        float rs = rsqrtf(s + EPSF);
        r[lane] = a * rs; r[lane + 32] = b * rs;
    } else {
        float rs = rsqrtf(s * (1.f / 64.f) + EPSF);
        r[lane] = a * rs * w[lane]; r[lane + 32] = b * rs * w[lane + 32];
    }
}

// beta = sigmoid(x @ Wb), Wb:[D,H]; one warp per (t,h)
__global__ void beta_k(const float* __restrict__ x, const float* __restrict__ Wb,
                       float* __restrict__ beta) {
    int gw = (blockIdx.x * blockDim.x + threadIdx.x) >> 5;
    int lane = threadIdx.x & 31;
    if (gw >= TT * HH) return;
    int t = gw / HH, hh = gw % HH;
    const float* xr = x + (size_t)t * DD;
    float s = 0.f;
    for (int i = lane; i < DD; i += 32) s += xr[i] * Wb[i * HH + hh];
#pragma unroll
    for (int o = 16; o > 0; o >>= 1) s += __shfl_xor_sync(0xffffffffu, s, o);
    if (lane == 0) beta[t * HH + hh] = 1.f / (1.f + expf(-s));
}

// recurrent delta rule: one block per head, 64 threads, S column in registers
__global__ __launch_bounds__(64) void delta_k(const float* __restrict__ q,
                                              const float* __restrict__ k,
                                              const float* __restrict__ v,
                                              const float* __restrict__ beta,
                                              float* __restrict__ o) {
    const int CH = 32;
    int head = blockIdx.x;
    int tid = threadIdx.x;  // = output column v
    __shared__ float qs[CH * 64], ks[CH * 64], vs[CH * 64], bs[CH];
    float S[64];
#pragma unroll
    for (int i = 0; i < 64; i++) S[i] = 0.f;

#pragma unroll 1
    for (int c = 0; c < TT / CH; c++) {
        for (int i = tid; i < CH * 64; i += 64) {
            int row = i >> 6, col = i & 63;
            size_t g = (size_t)(c * CH + row) * DD + head * 64 + col;
            qs[i] = q[g]; ks[i] = k[g]; vs[i] = v[g];
        }
        if (tid < CH) bs[tid] = beta[(c * CH + tid) * HH + head];
        __syncthreads();
#pragma unroll 1
        for (int s = 0; s < CH; s++) {
            const float* kp = ks + s * 64;
            const float* qp = qs + s * 64;
            float kS = 0.f;
#pragma unroll
            for (int j = 0; j < 64; j++) kS += kp[j] * S[j];
            float dv = bs[s] * (vs[s * 64 + tid] - kS);
            float ov = 0.f;
#pragma unroll
            for (int j = 0; j < 64; j++) { S[j] += kp[j] * dv; ov += qp[j] * S[j]; }
            o[(size_t)(c * CH + s) * DD + head * 64 + tid] = ov;
        }
        __syncthreads();
    }
}

__global__ void silu_mul_k(float* __restrict__ g, const float* __restrict__ u, int n) {
    int i = blockIdx.x * blockDim.x + threadIdx.x;
    if (i >= n) return;
    float x = g[i];
    g[i] = (x / (1.f + expf(-x))) * u[i];
}

__global__ void loss_rows_k(const float* __restrict__ logits, const int* __restrict__ tgt,
                            float* __restrict__ nll, float* __restrict__ msk) {
    int t = blockIdx.x;
    const float* r = logits + (size_t)t * VV;
    int tid = threadIdx.x;
    __shared__ float red[256];
    float m = -INFINITY;
    for (int i = tid; i < VV; i += 256) m = fmaxf(m, r[i]);
    red[tid] = m; __syncthreads();
    for (int o = 128; o > 0; o >>= 1) { if (tid < o) red[tid] = fmaxf(red[tid], red[tid + o]); __syncthreads(); }
    float rowmax = red[0]; __syncthreads();
    float s = 0.f;
    for (int i = tid; i < VV; i += 256) s += expf(r[i] - rowmax);
    red[tid] = s; __syncthreads();
    for (int o = 128; o > 0; o >>= 1) { if (tid < o) red[tid] += red[tid + o]; __syncthreads(); }
    if (tid == 0) {
        float denom = red[0];
        int tg = tgt[t];
        float mask = (tg >= 0) ? 1.f : 0.f;
        int tc = tg < 0 ? 0 : (tg > VV - 1 ? VV - 1 : tg);
        float lp = r[tc] - rowmax - logf(denom);
        nll[t] = -lp * mask;
        msk[t] = mask;
    }
}

__global__ void loss_reduce_k(const float* __restrict__ nll, const float* __restrict__ msk,
                              float* __restrict__ out) {
    int tid = threadIdx.x;
    __shared__ float r1[256], r2[256];
    float s = 0.f, c = 0.f;
    for (int i = tid; i < TT; i += 256) { s += nll[i]; c += msk[i]; }
    r1[tid] = s; r2[tid] = c; __syncthreads();
    for (int o = 128; o > 0; o >>= 1) {
        if (tid < o) { r1[tid] += r1[tid + o]; r2[tid] += r2[tid + o]; }
        __syncthreads();
    }
    if (tid == 0) out[0] = r1[0] / fmaxf(r2[0], 1.f);
}

// ---------------- host launcher ----------------
extern "C" void kernel_launch(void* const* d_in, const int* in_sizes, int n_in,
                              void* d_out, int out_size) {
    const int*   idx   = (const int*)d_in[0];
    const int*   tgt   = (const int*)d_in[1];
    const float* emb   = (const float*)d_in[2];
    const float* Wq    = (const float*)d_in[3];
    const float* Wk    = (const float*)d_in[4];
    const float* Wv    = (const float*)d_in[5];
    const float* convq = (const float*)d_in[6];
    const float* convk = (const float*)d_in[7];
    const float* convv = (const float*)d_in[8];
    const float* Wb    = (const float*)d_in[9];
    const float* onw   = (const float*)d_in[10];
    const float* Wo    = (const float*)d_in[11];
    const float* anw   = (const float*)d_in[12];
    const float* mnw   = (const float*)d_in[13];
    const float* Wg    = (const float*)d_in[14];
    const float* Wu    = (const float*)d_in[15];
    const float* Wd    = (const float*)d_in[16];
    const float* fnw   = (const float*)d_in[17];
    const float* lmh   = (const float*)d_in[18];
    float* out = (float*)d_out;

    float *hb, *xb, *t0, *t1, *t2, *qb, *kb, *vb, *ob, *bb, *gb, *ub, *nl, *mk, *lfb;
    cudaGetSymbolAddress((void**)&hb,  g_h);
    cudaGetSymbolAddress((void**)&xb,  g_x);
    cudaGetSymbolAddress((void**)&t0,  g_t0);
    cudaGetSymbolAddress((void**)&t1,  g_t1);
    cudaGetSymbolAddress((void**)&t2,  g_t2);
    cudaGetSymbolAddress((void**)&qb,  g_q);
    cudaGetSymbolAddress((void**)&kb,  g_k);
    cudaGetSymbolAddress((void**)&vb,  g_v);
    cudaGetSymbolAddress((void**)&ob,  g_o);
    cudaGetSymbolAddress((void**)&bb,  g_beta);
    cudaGetSymbolAddress((void**)&gb,  g_gate);
    cudaGetSymbolAddress((void**)&ub,  g_up);
    cudaGetSymbolAddress((void**)&nl,  g_nll);
    cudaGetSymbolAddress((void**)&mk,  g_msk);
    cudaGetSymbolAddress((void**)&lfb, g_logits_fb);

    const int ewarpBlocks = (TT * HH * 32 + 255) / 256;
    const int edBlocks = (TT * DD + 255) / 256;
    const int ffBlocks = (TT * FFF + 255) / 256;

    embed_k<<<TT, 256>>>(idx, emb, hb);

    for (int l = 0; l < LL; l++) {
        const float* Wq_l = Wq + (size_t)l * DD * DD;
        const float* Wk_l = Wk + (size_t)l * DD * DD;
        const float* Wv_l = Wv + (size_t)l * DD * DD;
        const float* cq_l = convq + (size_t)l * DD * KC;
        const float* ck_l = convk + (size_t)l * DD * KC;
        const float* cv_l = convv + (size_t)l * DD * KC;
        const float* Wb_l = Wb + (size_t)l * DD * HH;
        const float* on_l = onw + (size_t)l * DKK;
        const float* Wo_l = Wo + (size_t)l * DD * DD;
        const float* an_l = anw + (size_t)l * DD;
        const float* mn_l = mnw + (size_t)l * DD;
        const float* Wg_l = Wg + (size_t)l * DD * FFF;
        const float* Wu_l = Wu + (size_t)l * DD * FFF;
        const float* Wd_l = Wd + (size_t)l * FFF * DD;

        rmsnorm_k<<<TT, 256>>>(hb, an_l, xb, DD);

        dim3 gQK(DD / 64, TT / 128);
        sgemm_k<false><<<gQK, 256>>>(xb, Wq_l, t0, TT, DD, DD);
        sgemm_k<false><<<gQK, 256>>>(xb, Wk_l, t1, TT, DD, DD);
        sgemm_k<false><<<gQK, 256>>>(xb, Wv_l, t2, TT, DD, DD);

        conv_silu_k<<<edBlocks, 256>>>(t0, cq_l, qb);
        conv_silu_k<<<edBlocks, 256>>>(t1, ck_l, kb);
        conv_silu_k<<<edBlocks, 256>>>(t2, cv_l, vb);

        headnorm_k<<<ewarpBlocks, 256>>>(qb, nullptr, 0);
        headnorm_k<<<ewarpBlocks, 256>>>(kb, nullptr, 0);

        beta_k<<<ewarpBlocks, 256>>>(xb, Wb_l, bb);

        delta_k<<<HH, 64>>>(qb, kb, vb, bb, ob);

        headnorm_k<<<ewarpBlocks, 256>>>(ob, on_l, 1);

        sgemm_k<true><<<gQK, 256>>>(ob, Wo_l, hb, TT, DD, DD);

        rmsnorm_k<<<TT, 256>>>(hb, mn_l, xb, DD);

        dim3 gFF(FFF / 64, TT / 128);
        sgemm_k<false><<<gFF, 256>>>(xb, Wg_l, gb, TT, FFF, DD);
        sgemm_k<false><<<gFF, 256>>>(xb, Wu_l, ub, TT, FFF, DD);
        silu_mul_k<<<ffBlocks, 256>>>(gb, ub, TT * FFF);
        sgemm_k<true><<<gQK, 256>>>(gb, Wd_l, hb, TT, DD, FFF);
    }

    rmsnorm_k<<<TT, 256>>>(hb, fnw, xb, DD);

    const size_t LOGN = (size_t)TT * VV;
    float* logits = ((size_t)out_size >= LOGN) ? out : lfb;
    dim3 gV(VV / 64, TT / 128);
    sgemm_k<false><<<gV, 256>>>(xb, lmh, logits, TT, VV, DD);

    loss_rows_k<<<TT, 256>>>(logits, tgt, nl, mk);
    float* loss_dst = nullptr;
    if ((size_t)out_size >= LOGN + 1) loss_dst = out + LOGN;
    else if ((size_t)out_size < LOGN) loss_dst = out;  // loss-only output
    if (loss_dst) loss_reduce_k<<<1, 256>>>(nl, mk, loss_dst);
}

// round 3
// speedup vs baseline: 1.3862x; 1.3862x over previous
#include <cuda_runtime.h>
#include <cuda_bf16.h>
#include <math.h>
#include <stdint.h>

// Problem constants
#define TT   2048
#define DD   768
#define HH   12
#define DKK  64
#define FFF  2048
#define VV   50304
#define LL   12
#define KC   4
#define EPSF 1e-6f

// ---------------- scratch (__device__ globals; no allocation allowed) ----------------
__device__ float g_h[TT * DD];
__device__ float g_x[TT * DD];
__device__ float g_t0[TT * DD];
__device__ float g_t1[TT * DD];
__device__ float g_t2[TT * DD];
__device__ float g_q[TT * DD];
__device__ float g_k[TT * DD];
__device__ float g_v[TT * DD];
__device__ float g_o[TT * DD];
__device__ float g_beta[TT * HH];
__device__ float g_gate[TT * FFF];
__device__ float g_up[TT * FFF];
__device__ float g_nll[TT];
__device__ float g_msk[TT];
__device__ float g_logits_fb[(size_t)TT * VV];

// ---------------- helpers ----------------
__device__ __forceinline__ float to_tf32(float x) {
    uint32_t u;
    asm("cvt.rna.tf32.f32 %0, %1;" : "=r"(u) : "f"(x));
    return __uint_as_float(u);
}

__device__ __forceinline__ void mma_tf32(float* c, const uint32_t* a, const uint32_t* b) {
    asm volatile(
        "mma.sync.aligned.m16n8k8.row.col.f32.tf32.tf32.f32 "
        "{%0,%1,%2,%3}, {%4,%5,%6,%7}, {%8,%9}, {%0,%1,%2,%3};\n"
        : "+f"(c[0]), "+f"(c[1]), "+f"(c[2]), "+f"(c[3])
        : "r"(a[0]), "r"(a[1]), "r"(a[2]), "r"(a[3]), "r"(b[0]), "r"(b[1]));
}

// ---------------- kernels ----------------

__global__ void embed_k(const int* __restrict__ idx, const float* __restrict__ emb,
                        float* __restrict__ out) {
    int t = blockIdx.x;
    int row = idx[t];
    const float* src = emb + (size_t)row * DD;
    float* dst = out + (size_t)t * DD;
    for (int d = threadIdx.x; d < DD; d += blockDim.x) dst[d] = src[d];
}

__global__ void rmsnorm_k(const float* __restrict__ in, const float* __restrict__ w,
                          float* __restrict__ out, int n) {
    int t = blockIdx.x;
    const float* r = in + (size_t)t * n;
    float* wr = out + (size_t)t * n;
    int tid = threadIdx.x;
    __shared__ float red[256];
    float s = 0.f;
    for (int i = tid; i < n; i += 256) { float vv = r[i]; s += vv * vv; }
    red[tid] = s; __syncthreads();
    for (int o = 128; o > 0; o >>= 1) { if (tid < o) red[tid] += red[tid + o]; __syncthreads(); }
    float rs = rsqrtf(red[0] / (float)n + EPSF);
    for (int i = tid; i < n; i += 256) wr[i] = r[i] * rs * w[i];
}

// =======================================================================
// tf32x3 split-precision tensor-core GEMM (near-fp32 accuracy).
// C[M,N] (+)= A[M,K] @ B[K,N], row-major. BM=BN=128, BK=32, 256 threads
// (8 warps as 2(M) x 4(N), warp tile 64x32). blockIdx.z selects which of
// up to 3 (B, C) pairs (shared A) — fuses QKV / gate+up into one launch.
// Each operand split a = a_hi + a_lo (tf32 each); 3 MMAs per tile step.
// Requires M%128==0, N%128==0, K%32==0. Dynamic smem = 64 KB.
// =======================================================================
template <bool ADD>
__global__ __launch_bounds__(256) void tgemm3_k(const float* __restrict__ A,
                                                const float* __restrict__ B0,
                                                const float* __restrict__ B1,
                                                const float* __restrict__ B2,
                                                float* __restrict__ C0,
                                                float* __restrict__ C1,
                                                float* __restrict__ C2,
                                                int M, int N, int Kd) {
    extern __shared__ float sm[];
    float* As_hi = sm;            // [128][32] swizzled
    float* As_lo = sm + 4096;
    float* Bs_hi = sm + 8192;     // [32][128] swizzled
    float* Bs_lo = sm + 12288;

    const float* B = (blockIdx.z == 0) ? B0 : (blockIdx.z == 1 ? B1 : B2);
    float*       C = (blockIdx.z == 0) ? C0 : (blockIdx.z == 1 ? C1 : C2);

    const int bm = blockIdx.y * 128, bn = blockIdx.x * 128;
    const int tid = threadIdx.x;
    const int warp = tid >> 5, lane = tid & 31;
    const int warpM = warp >> 2;        // 0..1  (64 rows)
    const int warpN = warp & 3;         // 0..3  (32 cols)
    const int g = lane >> 2, t4 = lane & 3;

    float acc[4][4][4];
#pragma unroll
    for (int i = 0; i < 4; i++)
#pragma unroll
        for (int j = 0; j < 4; j++)
#pragma unroll
            for (int r = 0; r < 4; r++) acc[i][j][r] = 0.f;

    for (int k0 = 0; k0 < Kd; k0 += 32) {
        // ---- load A tile 128x32 (4 float4/thread), split hi/lo ----
#pragma unroll
        for (int i = 0; i < 4; i++) {
            int id = i * 256 + tid;
            int r = id >> 3, c4 = id & 7;
            float4 v = *reinterpret_cast<const float4*>(A + (size_t)(bm + r) * Kd + k0 + c4 * 4);
            float4 h, l;
            h.x = to_tf32(v.x); l.x = to_tf32(v.x - h.x);
            h.y = to_tf32(v.y); l.y = to_tf32(v.y - h.y);
            h.z = to_tf32(v.z); l.z = to_tf32(v.z - h.z);
            h.w = to_tf32(v.w); l.w = to_tf32(v.w - h.w);
            int off = r * 32 + ((c4 ^ (r & 7)) << 2);
            *reinterpret_cast<float4*>(&As_hi[off]) = h;
            *reinterpret_cast<float4*>(&As_lo[off]) = l;
        }
        // ---- load B tile 32x128 (4 float4/thread), split hi/lo ----
#pragma unroll
        for (int i = 0; i < 4; i++) {
            int id = i * 256 + tid;
            int k = id >> 5, n4 = id & 31;
            float4 v = *reinterpret_cast<const float4*>(B + (size_t)(k0 + k) * N + bn + n4 * 4);
            float4 h, l;
            h.x = to_tf32(v.x); l.x = to_tf32(v.x - h.x);
            h.y = to_tf32(v.y); l.y = to_tf32(v.y - h.y);
            h.z = to_tf32(v.z); l.z = to_tf32(v.z - h.z);
            h.w = to_tf32(v.w); l.w = to_tf32(v.w - h.w);
            int off = k * 128 + ((n4 ^ ((2 * k) & 7)) << 2);
            *reinterpret_cast<float4*>(&Bs_hi[off]) = h;
            *reinterpret_cast<float4*>(&Bs_lo[off]) = l;
        }
        __syncthreads();

#pragma unroll
        for (int ks = 0; ks < 4; ks++) {
            uint32_t ah[4][4], al[4][4];
#pragma unroll
            for (int mt = 0; mt < 4; mt++) {
                int r0 = warpM * 64 + mt * 16 + g;
                int r1 = r0 + 8;
                int c4a = ks * 2, c4b = ks * 2 + 1;
                int o0 = r0 * 32 + ((c4a ^ (r0 & 7)) << 2) + t4;
                int o1 = r1 * 32 + ((c4a ^ (r1 & 7)) << 2) + t4;
                int o2 = r0 * 32 + ((c4b ^ (r0 & 7)) << 2) + t4;
                int o3 = r1 * 32 + ((c4b ^ (r1 & 7)) << 2) + t4;
                ah[mt][0] = __float_as_uint(As_hi[o0]);
                ah[mt][1] = __float_as_uint(As_hi[o1]);
                ah[mt][2] = __float_as_uint(As_hi[o2]);
                ah[mt][3] = __float_as_uint(As_hi[o3]);
                al[mt][0] = __float_as_uint(As_lo[o0]);
                al[mt][1] = __float_as_uint(As_lo[o1]);
                al[mt][2] = __float_as_uint(As_lo[o2]);
                al[mt][3] = __float_as_uint(As_lo[o3]);
            }
            uint32_t bh[4][2], bl[4][2];
#pragma unroll
            for (int nt = 0; nt < 4; nt++) {
                int n = warpN * 32 + nt * 8 + g;
                int n4 = n >> 2, nl = n & 3;
                int kk0 = ks * 8 + t4, kk1 = kk0 + 4;
                int o0 = kk0 * 128 + ((n4 ^ ((2 * kk0) & 7)) << 2) + nl;
                int o1 = kk1 * 128 + ((n4 ^ ((2 * kk1) & 7)) << 2) + nl;
                bh[nt][0] = __float_as_uint(Bs_hi[o0]);
                bh[nt][1] = __float_as_uint(Bs_hi[o1]);
                bl[nt][0] = __float_as_uint(Bs_lo[o0]);
                bl[nt][1] = __float_as_uint(Bs_lo[o1]);
            }
#pragma unroll
            for (int mt = 0; mt < 4; mt++)
#pragma unroll
                for (int nt = 0; nt < 4; nt++) {
                    mma_tf32(acc[mt][nt], al[mt], bh[nt]);
                    mma_tf32(acc[mt][nt], ah[mt], bl[nt]);
                    mma_tf32(acc[mt][nt], ah[mt], bh[nt]);
                }
        }
        __syncthreads();
    }

    // epilogue
#pragma unroll
    for (int mt = 0; mt < 4; mt++) {
        int r0 = bm + warpM * 64 + mt * 16 + g;
#pragma unroll
        for (int nt = 0; nt < 4; nt++) {
            int c0 = bn + warpN * 32 + nt * 8 + 2 * t4;
            float* p0 = C + (size_t)r0 * N + c0;
            float* p1 = C + (size_t)(r0 + 8) * N + c0;
            if (ADD) {
                p0[0] += acc[mt][nt][0]; p0[1] += acc[mt][nt][1];
                p1[0] += acc[mt][nt][2]; p1[1] += acc[mt][nt][3];
            } else {
                p0[0] = acc[mt][nt][0]; p0[1] = acc[mt][nt][1];
                p1[0] = acc[mt][nt][2]; p1[1] = acc[mt][nt][3];
            }
        }
    }
}

// causal depthwise conv (K=4) + SiLU
__global__ void conv_silu_k(const float* __restrict__ x, const float* __restrict__ w,
                            float* __restrict__ out) {
    int i = blockIdx.x * blockDim.x + threadIdx.x;
    if (i >= TT * DD) return;
    int t = i / DD, d = i % DD;
    float acc = 0.f;
#pragma unroll
    for (int j = 0; j < KC; j++) {
        int tt = t - (KC - 1) + j;
        if (tt >= 0) acc += x[(size_t)tt * DD + d] * w[d * KC + j];
    }
    out[i] = acc / (1.f + expf(-acc));
}

// per-64-row norm. mode 0: l2norm. mode 1: rmsnorm * w[64]
__global__ void headnorm_k(float* __restrict__ data, const float* __restrict__ w, int mode) {
    int gw = (blockIdx.x * blockDim.x + threadIdx.x) >> 5;
    int lane = threadIdx.x & 31;
    if (gw >= TT * HH) return;
    float* r = data + (size_t)gw * 64;
    float a = r[lane], b = r[lane + 32];
    float s = a * a + b * b;
#pragma unroll
    for (int o = 16; o > 0; o >>= 1) s += __shfl_xor_sync(0xffffffffu, s, o);
    if (mode == 0) {
        float rs = rsqrtf(s + EPSF);
        r[lane] = a * rs; r[lane + 32] = b * rs;
    } else {
        float rs = rsqrtf(s * (1.f / 64.f) + EPSF);
        r[lane] = a * rs * w[lane]; r[lane + 32] = b * rs * w[lane + 32];
    }
}

__global__ void beta_k(const float* __restrict__ x, const float* __restrict__ Wb,
                       float* __restrict__ beta) {
    int gw = (blockIdx.x * blockDim.x + threadIdx.x) >> 5;
    int lane = threadIdx.x & 31;
    if (gw >= TT * HH) return;
    int t = gw / HH, hh = gw % HH;
    const float* xr = x + (size_t)t * DD;
    float s = 0.f;
    for (int i = lane; i < DD; i += 32) s += xr[i] * Wb[i * HH + hh];
#pragma unroll
    for (int o = 16; o > 0; o >>= 1) s += __shfl_xor_sync(0xffffffffu, s, o);
    if (lane == 0) beta[t * HH + hh] = 1.f / (1.f + expf(-s));
}

// recurrent delta rule: one block per head, 128 threads, 2-way k-split.
__global__ __launch_bounds__(128) void delta_k(const float* __restrict__ q,
                                               const float* __restrict__ k,
                                               const float* __restrict__ v,
                                               const float* __restrict__ beta,
                                               float* __restrict__ o) {
    const int CH = 32;
    int head = blockIdx.x;
    int tid = threadIdx.x;
    int col = tid >> 1;
    int half = tid & 1;
    __shared__ float qs[CH * 66], ks[CH * 66], vs[CH * 64], bs[CH];
    float S[32];
#pragma unroll
    for (int i = 0; i < 32; i++) S[i] = 0.f;

#pragma unroll 1
    for (int c = 0; c < TT / CH; c++) {
        for (int i = tid; i < CH * 64; i += 128) {
            int row = i >> 6, cc = i & 63;
            int so = row * 66 + (cc >> 5) * 33 + (cc & 31);
            size_t gaddr = (size_t)(c * CH + row) * DD + head * 64 + cc;
            qs[so] = q[gaddr];
            ks[so] = k[gaddr];
            vs[row * 64 + cc] = v[gaddr];
        }
        if (tid < CH) bs[tid] = beta[(c * CH + tid) * HH + head];
        __syncthreads();
#pragma unroll 1
        for (int s = 0; s < CH; s++) {
            const float* kp = ks + s * 66 + half * 33;
            const float* qp = qs + s * 66 + half * 33;
            float kS = 0.f;
#pragma unroll
            for (int j = 0; j < 32; j++) kS += kp[j] * S[j];
            kS += __shfl_xor_sync(0xffffffffu, kS, 1);
            float dv = bs[s] * (vs[s * 64 + col] - kS);
            float ov = 0.f;
#pragma unroll
            for (int j = 0; j < 32; j++) { S[j] += kp[j] * dv; ov += qp[j] * S[j]; }
            ov += __shfl_xor_sync(0xffffffffu, ov, 1);
            if (half == 0) o[(size_t)(c * CH + s) * DD + head * 64 + col] = ov;
        }
        __syncthreads();
    }
}

__global__ void silu_mul_k(float* __restrict__ g, const float* __restrict__ u, int n) {
    int i = blockIdx.x * blockDim.x + threadIdx.x;
    if (i >= n) return;
    float x = g[i];
    g[i] = (x / (1.f + expf(-x))) * u[i];
}

__global__ void loss_rows_k(const float* __restrict__ logits, const int* __restrict__ tgt,
                            float* __restrict__ nll, float* __restrict__ msk) {
    int t = blockIdx.x;
    const float* r = logits + (size_t)t * VV;
    int tid = threadIdx.x;
    __shared__ float red[256];
    float m = -INFINITY;
    for (int i = tid; i < VV; i += 256) m = fmaxf(m, r[i]);
    red[tid] = m; __syncthreads();
    for (int o = 128; o > 0; o >>= 1) { if (tid < o) red[tid] = fmaxf(red[tid], red[tid + o]); __syncthreads(); }
    float rowmax = red[0]; __syncthreads();
    float s = 0.f;
    for (int i = tid; i < VV; i += 256) s += expf(r[i] - rowmax);
    red[tid] = s; __syncthreads();
    for (int o = 128; o > 0; o >>= 1) { if (tid < o) red[tid] += red[tid + o]; __syncthreads(); }
    if (tid == 0) {
        float denom = red[0];
        int tg = tgt[t];
        float mask = (tg >= 0) ? 1.f : 0.f;
        int tc = tg < 0 ? 0 : (tg > VV - 1 ? VV - 1 : tg);
        float lp = r[tc] - rowmax - logf(denom);
        nll[t] = -lp * mask;
        msk[t] = mask;
    }
}

__global__ void loss_reduce_k(const float* __restrict__ nll, const float* __restrict__ msk,
                              float* __restrict__ out) {
    int tid = threadIdx.x;
    __shared__ float r1[256], r2[256];
    float s = 0.f, c = 0.f;
    for (int i = tid; i < TT; i += 256) { s += nll[i]; c += msk[i]; }
    r1[tid] = s; r2[tid] = c; __syncthreads();
    for (int o = 128; o > 0; o >>= 1) {
        if (tid < o) { r1[tid] += r1[tid + o]; r2[tid] += r2[tid + o]; }
        __syncthreads();
    }
    if (tid == 0) out[0] = r1[0] / fmaxf(r2[0], 1.f);
}

// ---------------- host launcher ----------------
extern "C" void kernel_launch(void* const* d_in, const int* in_sizes, int n_in,
                              void* d_out, int out_size) {
    const int*   idx   = (const int*)d_in[0];
    const int*   tgt   = (const int*)d_in[1];
    const float* emb   = (const float*)d_in[2];
    const float* Wq    = (const float*)d_in[3];
    const float* Wk    = (const float*)d_in[4];
    const float* Wv    = (const float*)d_in[5];
    const float* convq = (const float*)d_in[6];
    const float* convk = (const float*)d_in[7];
    const float* convv = (const float*)d_in[8];
    const float* Wb    = (const float*)d_in[9];
    const float* onw   = (const float*)d_in[10];
    const float* Wo    = (const float*)d_in[11];
    const float* anw   = (const float*)d_in[12];
    const float* mnw   = (const float*)d_in[13];
    const float* Wg    = (const float*)d_in[14];
    const float* Wu    = (const float*)d_in[15];
    const float* Wd    = (const float*)d_in[16];
    const float* fnw   = (const float*)d_in[17];
    const float* lmh   = (const float*)d_in[18];
    float* out = (float*)d_out;

    float *hb, *xb, *t0, *t1, *t2, *qb, *kb, *vb, *ob, *bb, *gb, *ub, *nl, *mk, *lfb;
    cudaGetSymbolAddress((void**)&hb,  g_h);
    cudaGetSymbolAddress((void**)&xb,  g_x);
    cudaGetSymbolAddress((void**)&t0,  g_t0);
    cudaGetSymbolAddress((void**)&t1,  g_t1);
    cudaGetSymbolAddress((void**)&t2,  g_t2);
    cudaGetSymbolAddress((void**)&qb,  g_q);
    cudaGetSymbolAddress((void**)&kb,  g_k);
    cudaGetSymbolAddress((void**)&vb,  g_v);
    cudaGetSymbolAddress((void**)&ob,  g_o);
    cudaGetSymbolAddress((void**)&bb,  g_beta);
    cudaGetSymbolAddress((void**)&gb,  g_gate);
    cudaGetSymbolAddress((void**)&ub,  g_up);
    cudaGetSymbolAddress((void**)&nl,  g_nll);
    cudaGetSymbolAddress((void**)&mk,  g_msk);
    cudaGetSymbolAddress((void**)&lfb, g_logits_fb);

    const int SMEM = 64 * 1024;
    static int attr_done = 0;
    if (!attr_done) {
        cudaFuncSetAttribute(tgemm3_k<false>, cudaFuncAttributeMaxDynamicSharedMemorySize, SMEM);
        cudaFuncSetAttribute(tgemm3_k<true>,  cudaFuncAttributeMaxDynamicSharedMemorySize, SMEM);
        attr_done = 1;
    }

    const int ewarpBlocks = (TT * HH * 32 + 255) / 256;
    const int edBlocks = (TT * DD + 255) / 256;
    const int ffBlocks = (TT * FFF + 255) / 256;

    embed_k<<<TT, 256>>>(idx, emb, hb);

    for (int l = 0; l < LL; l++) {
        const float* Wq_l = Wq + (size_t)l * DD * DD;
        const float* Wk_l = Wk + (size_t)l * DD * DD;
        const float* Wv_l = Wv + (size_t)l * DD * DD;
        const float* cq_l = convq + (size_t)l * DD * KC;
        const float* ck_l = convk + (size_t)l * DD * KC;
        const float* cv_l = convv + (size_t)l * DD * KC;
        const float* Wb_l = Wb + (size_t)l * DD * HH;
        const float* on_l = onw + (size_t)l * DKK;
        const float* Wo_l = Wo + (size_t)l * DD * DD;
        const float* an_l = anw + (size_t)l * DD;
        const float* mn_l = mnw + (size_t)l * DD;
        const float* Wg_l = Wg + (size_t)l * DD * FFF;
        const float* Wu_l = Wu + (size_t)l * DD * FFF;
        const float* Wd_l = Wd + (size_t)l * FFF * DD;

        rmsnorm_k<<<TT, 256>>>(hb, an_l, xb, DD);

        // QKV fused: one launch, blockIdx.z picks matrix
        dim3 gQKV(DD / 128, TT / 128, 3);
        tgemm3_k<false><<<gQKV, 256, SMEM>>>(xb, Wq_l, Wk_l, Wv_l, t0, t1, t2, TT, DD, DD);

        conv_silu_k<<<edBlocks, 256>>>(t0, cq_l, qb);
        conv_silu_k<<<edBlocks, 256>>>(t1, ck_l, kb);
        conv_silu_k<<<edBlocks, 256>>>(t2, cv_l, vb);

        headnorm_k<<<ewarpBlocks, 256>>>(qb, nullptr, 0);
        headnorm_k<<<ewarpBlocks, 256>>>(kb, nullptr, 0);

        beta_k<<<ewarpBlocks, 256>>>(xb, Wb_l, bb);

        delta_k<<<HH, 128>>>(qb, kb, vb, bb, ob);

        headnorm_k<<<ewarpBlocks, 256>>>(ob, on_l, 1);

        dim3 gD(DD / 128, TT / 128, 1);
        tgemm3_k<true><<<gD, 256, SMEM>>>(ob, Wo_l, Wo_l, Wo_l, hb, hb, hb, TT, DD, DD);

        rmsnorm_k<<<TT, 256>>>(hb, mn_l, xb, DD);

        // gate + up fused
        dim3 gGU(FFF / 128, TT / 128, 2);
        tgemm3_k<false><<<gGU, 256, SMEM>>>(xb, Wg_l, Wu_l, Wu_l, gb, ub, ub, TT, FFF, DD);

        silu_mul_k<<<ffBlocks, 256>>>(gb, ub, TT * FFF);

        tgemm3_k<true><<<gD, 256, SMEM>>>(gb, Wd_l, Wd_l, Wd_l, hb, hb, hb, TT, DD, FFF);
    }

    rmsnorm_k<<<TT, 256>>>(hb, fnw, xb, DD);

    const size_t LOGN = (size_t)TT * VV;
    float* logits = ((size_t)out_size >= LOGN) ? out : lfb;
    dim3 gV(VV / 128, TT / 128, 1);
    tgemm3_k<false><<<gV, 256, SMEM>>>(xb, lmh, lmh, lmh, logits, logits, logits, TT, VV, DD);

    loss_rows_k<<<TT, 256>>>(logits, tgt, nl, mk);
    float* loss_dst = nullptr;
    if ((size_t)out_size >= LOGN + 1) loss_dst = out + LOGN;
    else if ((size_t)out_size < LOGN) loss_dst = out;
    if (loss_dst) loss_reduce_k<<<1, 256>>>(nl, mk, loss_dst);
}

// round 4
// speedup vs baseline: 1.6789x; 1.2111x over previous
#include <cuda_runtime.h>
#include <cuda_bf16.h>
#include <math.h>
#include <stdint.h>

// Problem constants
#define TT   2048
#define DD   768
#define HH   12
#define DKK  64
#define FFF  2048
#define VV   50304
#define LL   12
#define KC   4
#define EPSF 1e-6f

// ---------------- scratch (__device__ globals; no allocation allowed) ----------------
__device__ float g_h[TT * DD];
__device__ float g_x[TT * DD];
__device__ float g_t0[TT * DD];
__device__ float g_t1[TT * DD];
__device__ float g_t2[TT * DD];
__device__ float g_q[TT * DD];
__device__ float g_k[TT * DD];
__device__ float g_v[TT * DD];
__device__ float g_o[TT * DD];
__device__ float g_beta[TT * HH];
__device__ float g_gate[TT * FFF];
__device__ float g_up[TT * FFF];
__device__ float g_nll[TT];
__device__ float g_msk[TT];
__device__ float g_logits_fb[(size_t)TT * VV];

// ---------------- helpers ----------------
__device__ __forceinline__ void mma_bf16(float* c, const uint32_t* a, const uint32_t* b) {
    asm volatile(
        "mma.sync.aligned.m16n8k16.row.col.f32.bf16.bf16.f32 "
        "{%0,%1,%2,%3}, {%4,%5,%6,%7}, {%8,%9}, {%0,%1,%2,%3};\n"
        : "+f"(c[0]), "+f"(c[1]), "+f"(c[2]), "+f"(c[3])
        : "r"(a[0]), "r"(a[1]), "r"(a[2]), "r"(a[3]), "r"(b[0]), "r"(b[1]));
}

// split x into bf16 hi + bf16 lo (hi+lo represents x to ~17 mantissa bits);
// pack pairs (x0 -> low half, x1 -> high half).
__device__ __forceinline__ void split_pack(float x0, float x1, uint32_t& hp, uint32_t& lp) {
    __nv_bfloat16 h0 = __float2bfloat16(x0), h1 = __float2bfloat16(x1);
    float f0 = __bfloat162float(h0), f1 = __bfloat162float(h1);
    __nv_bfloat16 l0 = __float2bfloat16(x0 - f0), l1 = __float2bfloat16(x1 - f1);
    hp = (uint32_t)__bfloat16_as_ushort(h0) | ((uint32_t)__bfloat16_as_ushort(h1) << 16);
    lp = (uint32_t)__bfloat16_as_ushort(l0) | ((uint32_t)__bfloat16_as_ushort(l1) << 16);
}

// ---------------- kernels ----------------

__global__ void embed_k(const int* __restrict__ idx, const float* __restrict__ emb,
                        float* __restrict__ out) {
    int t = blockIdx.x;
    int row = idx[t];
    const float* src = emb + (size_t)row * DD;
    float* dst = out + (size_t)t * DD;
    for (int d = threadIdx.x; d < DD; d += blockDim.x) dst[d] = src[d];
}

__global__ void rmsnorm_k(const float* __restrict__ in, const float* __restrict__ w,
                          float* __restrict__ out, int n) {
    int t = blockIdx.x;
    const float* r = in + (size_t)t * n;
    float* wr = out + (size_t)t * n;
    int tid = threadIdx.x;
    __shared__ float red[256];
    float s = 0.f;
    for (int i = tid; i < n; i += 256) { float vv = r[i]; s += vv * vv; }
    red[tid] = s; __syncthreads();
    for (int o = 128; o > 0; o >>= 1) { if (tid < o) red[tid] += red[tid + o]; __syncthreads(); }
    float rs = rsqrtf(red[0] / (float)n + EPSF);
    for (int i = tid; i < n; i += 256) wr[i] = r[i] * rs * w[i];
}

// =======================================================================
// bf16x3 split-precision tensor-core GEMM (near-fp32 accuracy).
// C[M,N] (+)= A[M,K] @ B[K,N], row-major. BM=BN=128, BK=32, 256 threads
// (8 warps = 2(M) x 4(N), warp tile 64x32). mma.m16n8k16.bf16.
// a = ah + al (bf16 each); C += ah*bh + al*bh + ah*bl.
// Double-buffered smem (2 x 32KB) with register staging.
// Smem word layouts (uint32 = bf16 pair along k for A, along k for B):
//   A: word(r, kw) at r*16 + (kw ^ 2*(r&7)),          kw = k/2 in 0..15
//   B: word(kw, n) at kw*128 + (n ^ ((kw*8)&127)),    pair = (k=2kw, k=2kw+1)
// blockIdx.z selects (B, C) pair (shared A) to fuse QKV / gate+up launches.
// Requires M%128==0, N%128==0, K%32==0. Dynamic smem = 64 KB.
// =======================================================================
template <bool ADD>
__global__ __launch_bounds__(256) void tbgemm_k(const float* __restrict__ A,
                                                const float* __restrict__ B0,
                                                const float* __restrict__ B1,
                                                const float* __restrict__ B2,
                                                float* __restrict__ C0,
                                                float* __restrict__ C1,
                                                float* __restrict__ C2,
                                                int M, int N, int Kd) {
    extern __shared__ uint32_t smw[];   // [2][8192]: AH(2048) AL(2048) BH(2048) BL(2048)

    const float* B = (blockIdx.z == 0) ? B0 : (blockIdx.z == 1 ? B1 : B2);
    float*       C = (blockIdx.z == 0) ? C0 : (blockIdx.z == 1 ? C1 : C2);

    const int bm = blockIdx.y * 128, bn = blockIdx.x * 128;
    const int tid = threadIdx.x;
    const int warp = tid >> 5, lane = tid & 31;
    const int warpM = warp >> 2;   // 0..1, 64 rows
    const int warpN = warp & 3;    // 0..3, 32 cols
    const int g = lane >> 2, t4 = lane & 3;

    float acc[4][4][4];
#pragma unroll
    for (int i = 0; i < 4; i++)
#pragma unroll
        for (int j = 0; j < 4; j++)
#pragma unroll
            for (int r = 0; r < 4; r++) acc[i][j][r] = 0.f;

    uint2 sa_h[4], sa_l[4];
    uint4 sb_h[2], sb_l[2];

    auto LOAD = [&](int kt) {
        int k0 = kt * 32;
#pragma unroll
        for (int i = 0; i < 4; i++) {
            int id = i * 256 + tid;
            int r = id >> 3, c4 = id & 7;
            float4 v = *reinterpret_cast<const float4*>(A + (size_t)(bm + r) * Kd + k0 + c4 * 4);
            split_pack(v.x, v.y, sa_h[i].x, sa_l[i].x);
            split_pack(v.z, v.w, sa_h[i].y, sa_l[i].y);
        }
#pragma unroll
        for (int i = 0; i < 2; i++) {
            int id = i * 256 + tid;
            int kw = id >> 5, n4 = id & 31;
            const float* p0 = B + (size_t)(k0 + 2 * kw) * N + bn + n4 * 4;
            float4 r0 = *reinterpret_cast<const float4*>(p0);
            float4 r1 = *reinterpret_cast<const float4*>(p0 + N);
            split_pack(r0.x, r1.x, sb_h[i].x, sb_l[i].x);
            split_pack(r0.y, r1.y, sb_h[i].y, sb_l[i].y);
            split_pack(r0.z, r1.z, sb_h[i].z, sb_l[i].z);
            split_pack(r0.w, r1.w, sb_h[i].w, sb_l[i].w);
        }
    };

    auto STORE = [&](int buf) {
        uint32_t* AH = smw + buf * 8192;
        uint32_t* AL = AH + 2048;
        uint32_t* BH = AH + 4096;
        uint32_t* BL = AH + 6144;
#pragma unroll
        for (int i = 0; i < 4; i++) {
            int id = i * 256 + tid;
            int r = id >> 3, c4 = id & 7;
            int off = r * 16 + ((c4 * 2) ^ ((r & 7) * 2));
            *reinterpret_cast<uint2*>(AH + off) = sa_h[i];
            *reinterpret_cast<uint2*>(AL + off) = sa_l[i];
        }
#pragma unroll
        for (int i = 0; i < 2; i++) {
            int id = i * 256 + tid;
            int kw = id >> 5, n4 = id & 31;
            int off = kw * 128 + ((n4 * 4) ^ ((kw * 8) & 127));
            *reinterpret_cast<uint4*>(BH + off) = sb_h[i];
            *reinterpret_cast<uint4*>(BL + off) = sb_l[i];
        }
    };

    auto COMPUTE = [&](int buf) {
        uint32_t* AH = smw + buf * 8192;
        uint32_t* AL = AH + 2048;
        uint32_t* BH = AH + 4096;
        uint32_t* BL = AH + 6144;
#pragma unroll
        for (int ks = 0; ks < 2; ks++) {
            uint32_t ah[4][4], al[4][4];
#pragma unroll
            for (int mt = 0; mt < 4; mt++) {
                int r0 = warpM * 64 + mt * 16 + g;
                int r1 = r0 + 8;
                int ka = ks * 8 + t4, kb = ka + 4;
                int o0 = r0 * 16 + (ka ^ ((r0 & 7) * 2));
                int o1 = r1 * 16 + (ka ^ ((r1 & 7) * 2));
                int o2 = r0 * 16 + (kb ^ ((r0 & 7) * 2));
                int o3 = r1 * 16 + (kb ^ ((r1 & 7) * 2));
                ah[mt][0] = AH[o0]; ah[mt][1] = AH[o1]; ah[mt][2] = AH[o2]; ah[mt][3] = AH[o3];
                al[mt][0] = AL[o0]; al[mt][1] = AL[o1]; al[mt][2] = AL[o2]; al[mt][3] = AL[o3];
            }
            uint32_t bh[4][2], bl[4][2];
#pragma unroll
            for (int nt = 0; nt < 4; nt++) {
                int n = warpN * 32 + nt * 8 + g;
                int k0w = ks * 8 + t4, k1w = k0w + 4;
                int o0 = k0w * 128 + (n ^ ((k0w * 8) & 127));
                int o1 = k1w * 128 + (n ^ ((k1w * 8) & 127));
                bh[nt][0] = BH[o0]; bh[nt][1] = BH[o1];
                bl[nt][0] = BL[o0]; bl[nt][1] = BL[o1];
            }
#pragma unroll
            for (int mt = 0; mt < 4; mt++)
#pragma unroll
                for (int nt = 0; nt < 4; nt++) {
                    mma_bf16(acc[mt][nt], al[mt], bh[nt]);
                    mma_bf16(acc[mt][nt], ah[mt], bl[nt]);
                    mma_bf16(acc[mt][nt], ah[mt], bh[nt]);
                }
        }
    };

    const int ntiles = Kd / 32;
    LOAD(0);
    STORE(0);
    __syncthreads();
    for (int kt = 0; kt < ntiles; kt++) {
        if (kt + 1 < ntiles) LOAD(kt + 1);
        COMPUTE(kt & 1);
        if (kt + 1 < ntiles) STORE((kt + 1) & 1);
        __syncthreads();
    }

    // epilogue (m16n8 C layout)
#pragma unroll
    for (int mt = 0; mt < 4; mt++) {
        int r0 = bm + warpM * 64 + mt * 16 + g;
#pragma unroll
        for (int nt = 0; nt < 4; nt++) {
            int c0 = bn + warpN * 32 + nt * 8 + 2 * t4;
            float* p0 = C + (size_t)r0 * N + c0;
            float* p1 = C + (size_t)(r0 + 8) * N + c0;
            if (ADD) {
                p0[0] += acc[mt][nt][0]; p0[1] += acc[mt][nt][1];
                p1[0] += acc[mt][nt][2]; p1[1] += acc[mt][nt][3];
            } else {
                p0[0] = acc[mt][nt][0]; p0[1] = acc[mt][nt][1];
                p1[0] = acc[mt][nt][2]; p1[1] = acc[mt][nt][3];
            }
        }
    }
}

// =======================================================================
// Fused post-QKV: causal depthwise conv(K=4)+SiLU for q,k,v; l2norm for
// q,k; beta = sigmoid(x @ Wb[:,h]). One block per (t, head), 64 threads.
// =======================================================================
__global__ __launch_bounds__(64) void postqkv_k(
    const float* __restrict__ t0, const float* __restrict__ t1, const float* __restrict__ t2,
    const float* __restrict__ cq, const float* __restrict__ ck, const float* __restrict__ cv,
    const float* __restrict__ x, const float* __restrict__ Wb,
    float* __restrict__ q, float* __restrict__ k, float* __restrict__ v,
    float* __restrict__ beta) {
    int t = blockIdx.x, h = blockIdx.y;
    int tid = threadIdx.x;
    int d = h * 64 + tid;
    int wrp = tid >> 5, lane = tid & 31;

    auto conv = [&](const float* src, const float* w) -> float {
        float acc = 0.f;
#pragma unroll
        for (int j = 0; j < KC; j++) {
            int tt = t - (KC - 1) + j;
            if (tt >= 0) acc += src[(size_t)tt * DD + d] * w[d * KC + j];
        }
        return acc / (1.f + expf(-acc));  // silu
    };
    float qv = conv(t0, cq);
    float kv = conv(t1, ck);
    float vv = conv(t2, cv);

    float sq = qv * qv, sk = kv * kv;
    float sb = 0.f;
    const float* xr = x + (size_t)t * DD;
    for (int i = tid; i < DD; i += 64) sb += xr[i] * Wb[i * HH + h];
#pragma unroll
    for (int o = 16; o > 0; o >>= 1) {
        sq += __shfl_xor_sync(0xffffffffu, sq, o);
        sk += __shfl_xor_sync(0xffffffffu, sk, o);
        sb += __shfl_xor_sync(0xffffffffu, sb, o);
    }
    __shared__ float red[3][2];
    if (lane == 0) { red[0][wrp] = sq; red[1][wrp] = sk; red[2][wrp] = sb; }
    __syncthreads();
    float rq = rsqrtf(red[0][0] + red[0][1] + EPSF);
    float rk = rsqrtf(red[1][0] + red[1][1] + EPSF);
    size_t gi = (size_t)t * DD + d;
    q[gi] = qv * rq;
    k[gi] = kv * rk;
    v[gi] = vv;
    if (tid == 0) beta[t * HH + h] = 1.f / (1.f + expf(-(red[2][0] + red[2][1])));
}

// per-64 rmsnorm * w (for delta output o)
__global__ void headnorm_k(float* __restrict__ data, const float* __restrict__ w) {
    int gw = (blockIdx.x * blockDim.x + threadIdx.x) >> 5;
    int lane = threadIdx.x & 31;
    if (gw >= TT * HH) return;
    float* r = data + (size_t)gw * 64;
    float a = r[lane], b = r[lane + 32];
    float s = a * a + b * b;
#pragma unroll
    for (int o = 16; o > 0; o >>= 1) s += __shfl_xor_sync(0xffffffffu, s, o);
    float rs = rsqrtf(s * (1.f / 64.f) + EPSF);
    r[lane] = a * rs * w[lane];
    r[lane + 32] = b * rs * w[lane + 32];
}

// recurrent delta rule: one block per head, 256 threads = 64 cols x 4-way k-split.
__global__ __launch_bounds__(256) void delta_k(const float* __restrict__ q,
                                               const float* __restrict__ k,
                                               const float* __restrict__ v,
                                               const float* __restrict__ beta,
                                               float* __restrict__ o) {
    const int CH = 32;
    int head = blockIdx.x;
    int tid = threadIdx.x;
    int col = tid >> 2;   // output column 0..63
    int qr = tid & 3;     // quarter of k-axis this thread owns
    __shared__ float qs[CH * 68], ks_[CH * 68], vs[CH * 64], bs[CH];
    float S[16];
#pragma unroll
    for (int i = 0; i < 16; i++) S[i] = 0.f;

#pragma unroll 1
    for (int c = 0; c < TT / CH; c++) {
        for (int i = tid; i < CH * 64; i += 256) {
            int row = i >> 6, cc = i & 63;
            int so = row * 68 + (cc >> 4) * 17 + (cc & 15);
            size_t gaddr = (size_t)(c * CH + row) * DD + head * 64 + cc;
            qs[so] = q[gaddr];
            ks_[so] = k[gaddr];
            vs[row * 64 + cc] = v[gaddr];
        }
        if (tid < CH) bs[tid] = beta[(c * CH + tid) * HH + head];
        __syncthreads();
#pragma unroll 1
        for (int s = 0; s < CH; s++) {
            const float* kp = ks_ + s * 68 + qr * 17;
            const float* qp = qs + s * 68 + qr * 17;
            float kS = 0.f;
#pragma unroll
            for (int j = 0; j < 16; j++) kS += kp[j] * S[j];
            kS += __shfl_xor_sync(0xffffffffu, kS, 1);
            kS += __shfl_xor_sync(0xffffffffu, kS, 2);
            float dv = bs[s] * (vs[s * 64 + col] - kS);
            float ov = 0.f;
#pragma unroll
            for (int j = 0; j < 16; j++) { S[j] += kp[j] * dv; ov += qp[j] * S[j]; }
            ov += __shfl_xor_sync(0xffffffffu, ov, 1);
            ov += __shfl_xor_sync(0xffffffffu, ov, 2);
            if (qr == 0) o[(size_t)(c * CH + s) * DD + head * 64 + col] = ov;
        }
        __syncthreads();
    }
}

__global__ void silu_mul_k(float* __restrict__ g, const float* __restrict__ u, int n) {
    int i = blockIdx.x * blockDim.x + threadIdx.x;
    if (i >= n) return;
    float x = g[i];
    g[i] = (x / (1.f + expf(-x))) * u[i];
}

__global__ void loss_rows_k(const float* __restrict__ logits, const int* __restrict__ tgt,
                            float* __restrict__ nll, float* __restrict__ msk) {
    int t = blockIdx.x;
    const float* r = logits + (size_t)t * VV;
    int tid = threadIdx.x;
    __shared__ float red[256];
    float m = -INFINITY;
    for (int i = tid; i < VV; i += 256) m = fmaxf(m, r[i]);
    red[tid] = m; __syncthreads();
    for (int o = 128; o > 0; o >>= 1) { if (tid < o) red[tid] = fmaxf(red[tid], red[tid + o]); __syncthreads(); }
    float rowmax = red[0]; __syncthreads();
    float s = 0.f;
    for (int i = tid; i < VV; i += 256) s += expf(r[i] - rowmax);
    red[tid] = s; __syncthreads();
    for (int o = 128; o > 0; o >>= 1) { if (tid < o) red[tid] += red[tid + o]; __syncthreads(); }
    if (tid == 0) {
        float denom = red[0];
        int tg = tgt[t];
        float mask = (tg >= 0) ? 1.f : 0.f;
        int tc = tg < 0 ? 0 : (tg > VV - 1 ? VV - 1 : tg);
        float lp = r[tc] - rowmax - logf(denom);
        nll[t] = -lp * mask;
        msk[t] = mask;
    }
}

__global__ void loss_reduce_k(const float* __restrict__ nll, const float* __restrict__ msk,
                              float* __restrict__ out) {
    int tid = threadIdx.x;
    __shared__ float r1[256], r2[256];
    float s = 0.f, c = 0.f;
    for (int i = tid; i < TT; i += 256) { s += nll[i]; c += msk[i]; }
    r1[tid] = s; r2[tid] = c; __syncthreads();
    for (int o = 128; o > 0; o >>= 1) {
        if (tid < o) { r1[tid] += r1[tid + o]; r2[tid] += r2[tid + o]; }
        __syncthreads();
    }
    if (tid == 0) out[0] = r1[0] / fmaxf(r2[0], 1.f);
}

// ---------------- host launcher ----------------
extern "C" void kernel_launch(void* const* d_in, const int* in_sizes, int n_in,
                              void* d_out, int out_size) {
    const int*   idx   = (const int*)d_in[0];
    const int*   tgt   = (const int*)d_in[1];
    const float* emb   = (const float*)d_in[2];
    const float* Wq    = (const float*)d_in[3];
    const float* Wk    = (const float*)d_in[4];
    const float* Wv    = (const float*)d_in[5];
    const float* convq = (const float*)d_in[6];
    const float* convk = (const float*)d_in[7];
    const float* convv = (const float*)d_in[8];
    const float* Wb    = (const float*)d_in[9];
    const float* onw   = (const float*)d_in[10];
    const float* Wo    = (const float*)d_in[11];
    const float* anw   = (const float*)d_in[12];
    const float* mnw   = (const float*)d_in[13];
    const float* Wg    = (const float*)d_in[14];
    const float* Wu    = (const float*)d_in[15];
    const float* Wd    = (const float*)d_in[16];
    const float* fnw   = (const float*)d_in[17];
    const float* lmh   = (const float*)d_in[18];
    float* out = (float*)d_out;

    float *hb, *xb, *t0, *t1, *t2, *qb, *kb, *vb, *ob, *bb, *gb, *ub, *nl, *mk, *lfb;
    cudaGetSymbolAddress((void**)&hb,  g_h);
    cudaGetSymbolAddress((void**)&xb,  g_x);
    cudaGetSymbolAddress((void**)&t0,  g_t0);
    cudaGetSymbolAddress((void**)&t1,  g_t1);
    cudaGetSymbolAddress((void**)&t2,  g_t2);
    cudaGetSymbolAddress((void**)&qb,  g_q);
    cudaGetSymbolAddress((void**)&kb,  g_k);
    cudaGetSymbolAddress((void**)&vb,  g_v);
    cudaGetSymbolAddress((void**)&ob,  g_o);
    cudaGetSymbolAddress((void**)&bb,  g_beta);
    cudaGetSymbolAddress((void**)&gb,  g_gate);
    cudaGetSymbolAddress((void**)&ub,  g_up);
    cudaGetSymbolAddress((void**)&nl,  g_nll);
    cudaGetSymbolAddress((void**)&mk,  g_msk);
    cudaGetSymbolAddress((void**)&lfb, g_logits_fb);

    const int SMEM = 64 * 1024;
    cudaFuncSetAttribute(tbgemm_k<false>, cudaFuncAttributeMaxDynamicSharedMemorySize, SMEM);
    cudaFuncSetAttribute(tbgemm_k<true>,  cudaFuncAttributeMaxDynamicSharedMemorySize, SMEM);

    const int ewarpBlocks = (TT * HH * 32 + 255) / 256;
    const int ffBlocks = (TT * FFF + 255) / 256;

    embed_k<<<TT, 256>>>(idx, emb, hb);

    for (int l = 0; l < LL; l++) {
        const float* Wq_l = Wq + (size_t)l * DD * DD;
        const float* Wk_l = Wk + (size_t)l * DD * DD;
        const float* Wv_l = Wv + (size_t)l * DD * DD;
        const float* cq_l = convq + (size_t)l * DD * KC;
        const float* ck_l = convk + (size_t)l * DD * KC;
        const float* cv_l = convv + (size_t)l * DD * KC;
        const float* Wb_l = Wb + (size_t)l * DD * HH;
        const float* on_l = onw + (size_t)l * DKK;
        const float* Wo_l = Wo + (size_t)l * DD * DD;
        const float* an_l = anw + (size_t)l * DD;
        const float* mn_l = mnw + (size_t)l * DD;
        const float* Wg_l = Wg + (size_t)l * DD * FFF;
        const float* Wu_l = Wu + (size_t)l * DD * FFF;
        const float* Wd_l = Wd + (size_t)l * FFF * DD;

        rmsnorm_k<<<TT, 256>>>(hb, an_l, xb, DD);

        dim3 gQKV(DD / 128, TT / 128, 3);
        tbgemm_k<false><<<gQKV, 256, SMEM>>>(xb, Wq_l, Wk_l, Wv_l, t0, t1, t2, TT, DD, DD);

        dim3 gPQ(TT, HH, 1);
        postqkv_k<<<gPQ, 64>>>(t0, t1, t2, cq_l, ck_l, cv_l, xb, Wb_l, qb, kb, vb, bb);

        delta_k<<<HH, 256>>>(qb, kb, vb, bb, ob);

        headnorm_k<<<ewarpBlocks, 256>>>(ob, on_l);

        dim3 gD(DD / 128, TT / 128, 1);
        tbgemm_k<true><<<gD, 256, SMEM>>>(ob, Wo_l, Wo_l, Wo_l, hb, hb, hb, TT, DD, DD);

        rmsnorm_k<<<TT, 256>>>(hb, mn_l, xb, DD);

        dim3 gGU(FFF / 128, TT / 128, 2);
        tbgemm_k<false><<<gGU, 256, SMEM>>>(xb, Wg_l, Wu_l, Wu_l, gb, ub, ub, TT, FFF, DD);

        silu_mul_k<<<ffBlocks, 256>>>(gb, ub, TT * FFF);

        tbgemm_k<true><<<gD, 256, SMEM>>>(gb, Wd_l, Wd_l, Wd_l, hb, hb, hb, TT, DD, FFF);
    }

    rmsnorm_k<<<TT, 256>>>(hb, fnw, xb, DD);

    const size_t LOGN = (size_t)TT * VV;
    float* logits = ((size_t)out_size >= LOGN) ? out : lfb;
    dim3 gV(VV / 128, TT / 128, 1);
    tbgemm_k<false><<<gV, 256, SMEM>>>(xb, lmh, lmh, lmh, logits, logits, logits, TT, VV, DD);

    loss_rows_k<<<TT, 256>>>(logits, tgt, nl, mk);
    float* loss_dst = nullptr;
    if ((size_t)out_size >= LOGN + 1) loss_dst = out + LOGN;
    else if ((size_t)out_size < LOGN) loss_dst = out;
    if (loss_dst) loss_reduce_k<<<1, 256>>>(nl, mk, loss_dst);
}

// round 5
// speedup vs baseline: 2.0091x; 1.1967x over previous
#include <cuda_runtime.h>
#include <cuda_bf16.h>
#include <math.h>
#include <stdint.h>

// Problem constants
#define TT   2048
#define DD   768
#define HH   12
#define DKK  64
#define FFF  2048
#define VV   50304
#define LL   12
#define KC   4
#define EPSF 1e-6f

// packed word counts per matrix (word = uint32 = 2 bf16 packed along K)
#define WSM 294912     // 384*768   (Wq/Wk/Wv/Wo per layer)
#define WGU 786432     // 384*2048  (Wgate/Wup per layer)
#define WDN 786432     // 1024*768  (Wdown per layer)
#define WLM 19316736   // 384*50304 (lm_head)

// ---------------- scratch (__device__ globals; no allocation allowed) ----------------
__device__ float g_h[TT * DD];
__device__ float g_x[TT * DD];
__device__ float g_t0[TT * DD];
__device__ float g_t1[TT * DD];
__device__ float g_t2[TT * DD];
__device__ float g_q[TT * DD];
__device__ float g_k[TT * DD];
__device__ float g_v[TT * DD];
__device__ float g_o[TT * DD];
__device__ float g_beta[TT * HH];
__device__ float g_gate[TT * FFF];
__device__ float g_up[TT * FFF];
__device__ float g_nll[TT];
__device__ float g_msk[TT];
__device__ float g_logits_fb[(size_t)TT * VV];

// packed activation buffer (A operand), max Kd=2048 -> 1024 words/row
__device__ uint32_t g_pA_h[TT * 1024];
__device__ uint32_t g_pA_l[TT * 1024];

// packed weights
__device__ uint32_t g_Wq_h[LL * WSM]; __device__ uint32_t g_Wq_l[LL * WSM];
__device__ uint32_t g_Wk_h[LL * WSM]; __device__ uint32_t g_Wk_l[LL * WSM];
__device__ uint32_t g_Wv_h[LL * WSM]; __device__ uint32_t g_Wv_l[LL * WSM];
__device__ uint32_t g_Wo_h[LL * WSM]; __device__ uint32_t g_Wo_l[LL * WSM];
__device__ uint32_t g_Wg_h[LL * WGU]; __device__ uint32_t g_Wg_l[LL * WGU];
__device__ uint32_t g_Wu_h[LL * WGU]; __device__ uint32_t g_Wu_l[LL * WGU];
__device__ uint32_t g_Wd_h[LL * WDN]; __device__ uint32_t g_Wd_l[LL * WDN];
__device__ uint32_t g_Lm_h[WLM];      __device__ uint32_t g_Lm_l[WLM];

// ---------------- helpers ----------------
__device__ __forceinline__ void mma_bf16(float* c, const uint32_t* a, const uint32_t* b) {
    asm volatile(
        "mma.sync.aligned.m16n8k16.row.col.f32.bf16.bf16.f32 "
        "{%0,%1,%2,%3}, {%4,%5,%6,%7}, {%8,%9}, {%0,%1,%2,%3};\n"
        : "+f"(c[0]), "+f"(c[1]), "+f"(c[2]), "+f"(c[3])
        : "r"(a[0]), "r"(a[1]), "r"(a[2]), "r"(a[3]), "r"(b[0]), "r"(b[1]));
}

// split (x0, x1) into bf16 hi/lo pairs, packed (x0 -> low half).
__device__ __forceinline__ void split_pack(float x0, float x1, uint32_t& hp, uint32_t& lp) {
    __nv_bfloat16 h0 = __float2bfloat16(x0), h1 = __float2bfloat16(x1);
    float f0 = __bfloat162float(h0), f1 = __bfloat162float(h1);
    __nv_bfloat16 l0 = __float2bfloat16(x0 - f0), l1 = __float2bfloat16(x1 - f1);
    hp = (uint32_t)__bfloat16_as_ushort(h0) | ((uint32_t)__bfloat16_as_ushort(h1) << 16);
    lp = (uint32_t)__bfloat16_as_ushort(l0) | ((uint32_t)__bfloat16_as_ushort(l1) << 16);
}

// ---------------- kernels ----------------

__global__ void embed_k(const int* __restrict__ idx, const float* __restrict__ emb,
                        float* __restrict__ out) {
    int t = blockIdx.x;
    int row = idx[t];
    const float* src = emb + (size_t)row * DD;
    float* dst = out + (size_t)t * DD;
    for (int d = threadIdx.x; d < DD; d += blockDim.x) dst[d] = src[d];
}

// pack weights: src [count][2*Kw][N] fp32 -> dstH/dstL [count][Kw][N] words
__global__ void pack_w_k(const float* __restrict__ src, uint32_t* __restrict__ dH,
                         uint32_t* __restrict__ dL, int Kw, int N) {
    size_t nw = (size_t)Kw * N;
    size_t bs = (size_t)blockIdx.z * 2u * nw;
    size_t bd = (size_t)blockIdx.z * nw;
    for (size_t i = (size_t)blockIdx.x * blockDim.x + threadIdx.x; i < nw;
         i += (size_t)gridDim.x * blockDim.x) {
        size_t kw = i / N, n = i % N;
        float a0 = src[bs + (2 * kw) * N + n];
        float a1 = src[bs + (2 * kw + 1) * N + n];
        uint32_t h, l;
        split_pack(a0, a1, h, l);
        dH[bd + i] = h;
        dL[bd + i] = l;
    }
}

// rmsnorm over n cols; writes optional fp32 out and packed hi/lo (row stride n/2 words)
__global__ void rmsnorm_pack_k(const float* __restrict__ in, const float* __restrict__ w,
                               float* __restrict__ outf,
                               uint32_t* __restrict__ pH, uint32_t* __restrict__ pL, int n) {
    int t = blockIdx.x;
    const float* r = in + (size_t)t * n;
    int tid = threadIdx.x;
    __shared__ float red[256];
    float s = 0.f;
    for (int i = tid; i < n; i += 256) { float vv = r[i]; s += vv * vv; }
    red[tid] = s; __syncthreads();
    for (int o = 128; o > 0; o >>= 1) { if (tid < o) red[tid] += red[tid + o]; __syncthreads(); }
    float rs = rsqrtf(red[0] / (float)n + EPSF);
    int nw = n >> 1;
    for (int i = tid; i < nw; i += 256) {
        float x0 = r[2 * i] * rs * w[2 * i];
        float x1 = r[2 * i + 1] * rs * w[2 * i + 1];
        if (outf) { outf[(size_t)t * n + 2 * i] = x0; outf[(size_t)t * n + 2 * i + 1] = x1; }
        uint32_t h, l;
        split_pack(x0, x1, h, l);
        pH[(size_t)t * nw + i] = h;
        pL[(size_t)t * nw + i] = l;
    }
}

// =======================================================================
// bf16x3 split-precision tensor-core GEMM with PRE-PACKED operands.
// C[M,N] (+)= A[M,K] @ B[K,N]. BM = MT*32 (MT=4 ->128, MT=2 ->64), BN=128,
// BK=32, 256 threads (8 warps = 2(M) x 4(N)). mma.m16n8k16.bf16,
// C += ah*bh + al*bh + ah*bl. Double-buffered smem, register staging.
// A packed [M][Kd/2] words; B packed [Kd/2][N] words (word = k-pair bf16).
// Smem word layouts (conflict-free, verified in round 4):
//   A: word(r, kw) at r*16 + (kw ^ 2*(r&7))
//   B: word(kw, n) at kw*128 + (n ^ ((kw*8)&127))
// blockIdx.z selects (B, C) pair (shared A).
// Requires M%BM==0, N%128==0, K%32==0.
// =======================================================================
template <bool ADD, int MT>
__global__ __launch_bounds__(256) void tbgemm_k(
    const uint32_t* __restrict__ AHg, const uint32_t* __restrict__ ALg,
    const uint32_t* __restrict__ B0H, const uint32_t* __restrict__ B0L,
    const uint32_t* __restrict__ B1H, const uint32_t* __restrict__ B1L,
    const uint32_t* __restrict__ B2H, const uint32_t* __restrict__ B2L,
    float* __restrict__ C0, float* __restrict__ C1, float* __restrict__ C2,
    int M, int N, int Kd) {
    extern __shared__ uint32_t smw[];
    const int BM = MT * 32;
    const int AW = MT * 512;           // A words per (hi or lo) section
    const int BUF = AW * 2 + 4096;     // words per stage buffer
    const int Kw = Kd >> 1;

    const uint32_t* BHg = (blockIdx.z == 0) ? B0H : (blockIdx.z == 1 ? B1H : B2H);
    const uint32_t* BLg = (blockIdx.z == 0) ? B0L : (blockIdx.z == 1 ? B1L : B2L);
    float*          C   = (blockIdx.z == 0) ? C0  : (blockIdx.z == 1 ? C1  : C2);

    const int bm = blockIdx.y * BM, bn = blockIdx.x * 128;
    const int tid = threadIdx.x;
    const int warp = tid >> 5, lane = tid & 31;
    const int warpM = warp >> 2;   // 0..1
    const int warpN = warp & 3;    // 0..3
    const int g = lane >> 2, t4 = lane & 3;

    float acc[MT][4][4];
#pragma unroll
    for (int i = 0; i < MT; i++)
#pragma unroll
        for (int j = 0; j < 4; j++)
#pragma unroll
            for (int r = 0; r < 4; r++) acc[i][j][r] = 0.f;

    uint2 sa_h[MT], sa_l[MT];
    uint4 sb_h[2], sb_l[2];

    auto LOAD = [&](int kt) {
#pragma unroll
        for (int i = 0; i < MT; i++) {
            int id = i * 256 + tid;
            int r = id >> 3, c4 = id & 7;
            size_t off = (size_t)(bm + r) * Kw + kt * 16 + c4 * 2;
            sa_h[i] = *reinterpret_cast<const uint2*>(AHg + off);
            sa_l[i] = *reinterpret_cast<const uint2*>(ALg + off);
        }
#pragma unroll
        for (int i = 0; i < 2; i++) {
            int id = i * 256 + tid;
            int kw = id >> 5, n4 = id & 31;
            size_t off = (size_t)(kt * 16 + kw) * N + bn + n4 * 4;
            sb_h[i] = *reinterpret_cast<const uint4*>(BHg + off);
            sb_l[i] = *reinterpret_cast<const uint4*>(BLg + off);
        }
    };

    auto STORE = [&](int buf) {
        uint32_t* AH = smw + buf * BUF;
        uint32_t* AL = AH + AW;
        uint32_t* BH = AH + 2 * AW;
        uint32_t* BL = BH + 2048;
#pragma unroll
        for (int i = 0; i < MT; i++) {
            int id = i * 256 + tid;
            int r = id >> 3, c4 = id & 7;
            int off = r * 16 + ((c4 * 2) ^ ((r & 7) * 2));
            *reinterpret_cast<uint2*>(AH + off) = sa_h[i];
            *reinterpret_cast<uint2*>(AL + off) = sa_l[i];
        }
#pragma unroll
        for (int i = 0; i < 2; i++) {
            int id = i * 256 + tid;
            int kw = id >> 5, n4 = id & 31;
            int off = kw * 128 + ((n4 * 4) ^ ((kw * 8) & 127));
            *reinterpret_cast<uint4*>(BH + off) = sb_h[i];
            *reinterpret_cast<uint4*>(BL + off) = sb_l[i];
        }
    };

    auto COMPUTE = [&](int buf) {
        uint32_t* AH = smw + buf * BUF;
        uint32_t* AL = AH + AW;
        uint32_t* BH = AH + 2 * AW;
        uint32_t* BL = BH + 2048;
#pragma unroll
        for (int ks = 0; ks < 2; ks++) {
            uint32_t ah[MT][4], al[MT][4];
#pragma unroll
            for (int mt = 0; mt < MT; mt++) {
                int r0 = warpM * (MT * 16) + mt * 16 + g;
                int r1 = r0 + 8;
                int ka = ks * 8 + t4, kb = ka + 4;
                int o0 = r0 * 16 + (ka ^ ((r0 & 7) * 2));
                int o1 = r1 * 16 + (ka ^ ((r1 & 7) * 2));
                int o2 = r0 * 16 + (kb ^ ((r0 & 7) * 2));
                int o3 = r1 * 16 + (kb ^ ((r1 & 7) * 2));
                ah[mt][0] = AH[o0]; ah[mt][1] = AH[o1]; ah[mt][2] = AH[o2]; ah[mt][3] = AH[o3];
                al[mt][0] = AL[o0]; al[mt][1] = AL[o1]; al[mt][2] = AL[o2]; al[mt][3] = AL[o3];
            }
            uint32_t bh[4][2], bl[4][2];
#pragma unroll
            for (int nt = 0; nt < 4; nt++) {
                int n = warpN * 32 + nt * 8 + g;
                int k0w = ks * 8 + t4, k1w = k0w + 4;
                int o0 = k0w * 128 + (n ^ ((k0w * 8) & 127));
                int o1 = k1w * 128 + (n ^ ((k1w * 8) & 127));
                bh[nt][0] = BH[o0]; bh[nt][1] = BH[o1];
                bl[nt][0] = BL[o0]; bl[nt][1] = BL[o1];
            }
#pragma unroll
            for (int mt = 0; mt < MT; mt++)
#pragma unroll
                for (int nt = 0; nt < 4; nt++) {
                    mma_bf16(acc[mt][nt], al[mt], bh[nt]);
                    mma_bf16(acc[mt][nt], ah[mt], bl[nt]);
                    mma_bf16(acc[mt][nt], ah[mt], bh[nt]);
                }
        }
    };

    const int ntiles = Kd / 32;
    LOAD(0);
    STORE(0);
    __syncthreads();
    for (int kt = 0; kt < ntiles; kt++) {
        if (kt + 1 < ntiles) LOAD(kt + 1);
        COMPUTE(kt & 1);
        if (kt + 1 < ntiles) STORE((kt + 1) & 1);
        __syncthreads();
    }

#pragma unroll
    for (int mt = 0; mt < MT; mt++) {
        int r0 = bm + warpM * (MT * 16) + mt * 16 + g;
#pragma unroll
        for (int nt = 0; nt < 4; nt++) {
            int c0 = bn + warpN * 32 + nt * 8 + 2 * t4;
            float* p0 = C + (size_t)r0 * N + c0;
            float* p1 = C + (size_t)(r0 + 8) * N + c0;
            if (ADD) {
                p0[0] += acc[mt][nt][0]; p0[1] += acc[mt][nt][1];
                p1[0] += acc[mt][nt][2]; p1[1] += acc[mt][nt][3];
            } else {
                p0[0] = acc[mt][nt][0]; p0[1] = acc[mt][nt][1];
                p1[0] = acc[mt][nt][2]; p1[1] = acc[mt][nt][3];
            }
        }
    }
}

// =======================================================================
// Fused post-QKV: causal depthwise conv(K=4)+SiLU for q,k,v; l2norm for
// q,k; beta = sigmoid(x @ Wb[:,h]). One block per (t, head), 64 threads.
// =======================================================================
__global__ __launch_bounds__(64) void postqkv_k(
    const float* __restrict__ t0, const float* __restrict__ t1, const float* __restrict__ t2,
    const float* __restrict__ cq, const float* __restrict__ ck, const float* __restrict__ cv,
    const float* __restrict__ x, const float* __restrict__ Wb,
    float* __restrict__ q, float* __restrict__ k, float* __restrict__ v,
    float* __restrict__ beta) {
    int t = blockIdx.x, h = blockIdx.y;
    int tid = threadIdx.x;
    int d = h * 64 + tid;
    int wrp = tid >> 5, lane = tid & 31;

    auto conv = [&](const float* src, const float* w) -> float {
        float acc = 0.f;
#pragma unroll
        for (int j = 0; j < KC; j++) {
            int tt = t - (KC - 1) + j;
            if (tt >= 0) acc += src[(size_t)tt * DD + d] * w[d * KC + j];
        }
        return acc / (1.f + expf(-acc));  // silu
    };
    float qv = conv(t0, cq);
    float kv = conv(t1, ck);
    float vv = conv(t2, cv);

    float sq = qv * qv, sk = kv * kv;
    float sb = 0.f;
    const float* xr = x + (size_t)t * DD;
    for (int i = tid; i < DD; i += 64) sb += xr[i] * Wb[i * HH + h];
#pragma unroll
    for (int o = 16; o > 0; o >>= 1) {
        sq += __shfl_xor_sync(0xffffffffu, sq, o);
        sk += __shfl_xor_sync(0xffffffffu, sk, o);
        sb += __shfl_xor_sync(0xffffffffu, sb, o);
    }
    __shared__ float red[3][2];
    if (lane == 0) { red[0][wrp] = sq; red[1][wrp] = sk; red[2][wrp] = sb; }
    __syncthreads();
    float rq = rsqrtf(red[0][0] + red[0][1] + EPSF);
    float rk = rsqrtf(red[1][0] + red[1][1] + EPSF);
    size_t gi = (size_t)t * DD + d;
    q[gi] = qv * rq;
    k[gi] = kv * rk;
    v[gi] = vv;
    if (tid == 0) beta[t * HH + h] = 1.f / (1.f + expf(-(red[2][0] + red[2][1])));
}

// per-64 rmsnorm * w of delta output; writes PACKED words only (feeds Wo GEMM)
__global__ void headnorm_pack_k(const float* __restrict__ o, const float* __restrict__ w,
                                uint32_t* __restrict__ pH, uint32_t* __restrict__ pL) {
    int gw = (blockIdx.x * blockDim.x + threadIdx.x) >> 5;
    int lane = threadIdx.x & 31;
    if (gw >= TT * HH) return;
    const float* r = o + (size_t)gw * 64;
    float a = r[2 * lane], b = r[2 * lane + 1];
    float s = a * a + b * b;
#pragma unroll
    for (int os = 16; os > 0; os >>= 1) s += __shfl_xor_sync(0xffffffffu, s, os);
    float rs = rsqrtf(s * (1.f / 64.f) + EPSF);
    int t = gw / HH, h = gw % HH;
    uint32_t hw, lw;
    split_pack(a * rs * w[2 * lane], b * rs * w[2 * lane + 1], hw, lw);
    size_t wi = (size_t)t * 384 + h * 32 + lane;
    pH[wi] = hw;
    pL[wi] = lw;
}

// recurrent delta rule: one block per head, 256 threads = 64 cols x 4-way k-split.
__global__ __launch_bounds__(256) void delta_k(const float* __restrict__ q,
                                               const float* __restrict__ k,
                                               const float* __restrict__ v,
                                               const float* __restrict__ beta,
                                               float* __restrict__ o) {
    const int CH = 32;
    int head = blockIdx.x;
    int tid = threadIdx.x;
    int col = tid >> 2;
    int qr = tid & 3;
    __shared__ float qs[CH * 68], ks_[CH * 68], vs[CH * 64], bs[CH];
    float S[16];
#pragma unroll
    for (int i = 0; i < 16; i++) S[i] = 0.f;

#pragma unroll 1
    for (int c = 0; c < TT / CH; c++) {
        for (int i = tid; i < CH * 64; i += 256) {
            int row = i >> 6, cc = i & 63;
            int so = row * 68 + (cc >> 4) * 17 + (cc & 15);
            size_t gaddr = (size_t)(c * CH + row) * DD + head * 64 + cc;
            qs[so] = q[gaddr];
            ks_[so] = k[gaddr];
            vs[row * 64 + cc] = v[gaddr];
        }
        if (tid < CH) bs[tid] = beta[(c * CH + tid) * HH + head];
        __syncthreads();
#pragma unroll 1
        for (int s = 0; s < CH; s++) {
            const float* kp = ks_ + s * 68 + qr * 17;
            const float* qp = qs + s * 68 + qr * 17;
            float kS = 0.f;
#pragma unroll
            for (int j = 0; j < 16; j++) kS += kp[j] * S[j];
            kS += __shfl_xor_sync(0xffffffffu, kS, 1);
            kS += __shfl_xor_sync(0xffffffffu, kS, 2);
            float dv = bs[s] * (vs[s * 64 + col] - kS);
            float ov = 0.f;
#pragma unroll
            for (int j = 0; j < 16; j++) { S[j] += kp[j] * dv; ov += qp[j] * S[j]; }
            ov += __shfl_xor_sync(0xffffffffu, ov, 1);
            ov += __shfl_xor_sync(0xffffffffu, ov, 2);
            if (qr == 0) o[(size_t)(c * CH + s) * DD + head * 64 + col] = ov;
        }
        __syncthreads();
    }
}

// silu(g)*u, writes packed words (feeds down-proj GEMM); i indexes element pairs
__global__ void silu_mul_pack_k(const float* __restrict__ g, const float* __restrict__ u,
                                uint32_t* __restrict__ pH, uint32_t* __restrict__ pL) {
    int i = blockIdx.x * blockDim.x + threadIdx.x;
    if (i >= TT * FFF / 2) return;
    float g0 = g[2 * i], g1 = g[2 * i + 1];
    float y0 = (g0 / (1.f + expf(-g0))) * u[2 * i];
    float y1 = (g1 / (1.f + expf(-g1))) * u[2 * i + 1];
    uint32_t h, l;
    split_pack(y0, y1, h, l);
    pH[i] = h;
    pL[i] = l;
}

__global__ void loss_rows_k(const float* __restrict__ logits, const int* __restrict__ tgt,
                            float* __restrict__ nll, float* __restrict__ msk) {
    int t = blockIdx.x;
    const float* r = logits + (size_t)t * VV;
    int tid = threadIdx.x;
    __shared__ float red[256];
    float m = -INFINITY;
    for (int i = tid; i < VV; i += 256) m = fmaxf(m, r[i]);
    red[tid] = m; __syncthreads();
    for (int o = 128; o > 0; o >>= 1) { if (tid < o) red[tid] = fmaxf(red[tid], red[tid + o]); __syncthreads(); }
    float rowmax = red[0]; __syncthreads();
    float s = 0.f;
    for (int i = tid; i < VV; i += 256) s += expf(r[i] - rowmax);
    red[tid] = s; __syncthreads();
    for (int o = 128; o > 0; o >>= 1) { if (tid < o) red[tid] += red[tid + o]; __syncthreads(); }
    if (tid == 0) {
        float denom = red[0];
        int tg = tgt[t];
        float mask = (tg >= 0) ? 1.f : 0.f;
        int tc = tg < 0 ? 0 : (tg > VV - 1 ? VV - 1 : tg);
        float lp = r[tc] - rowmax - logf(denom);
        nll[t] = -lp * mask;
        msk[t] = mask;
    }
}

__global__ void loss_reduce_k(const float* __restrict__ nll, const float* __restrict__ msk,
                              float* __restrict__ out) {
    int tid = threadIdx.x;
    __shared__ float r1[256], r2[256];
    float s = 0.f, c = 0.f;
    for (int i = tid; i < TT; i += 256) { s += nll[i]; c += msk[i]; }
    r1[tid] = s; r2[tid] = c; __syncthreads();
    for (int o = 128; o > 0; o >>= 1) {
        if (tid < o) { r1[tid] += r1[tid + o]; r2[tid] += r2[tid + o]; }
        __syncthreads();
    }
    if (tid == 0) out[0] = r1[0] / fmaxf(r2[0], 1.f);
}

// ---------------- host launcher ----------------
extern "C" void kernel_launch(void* const* d_in, const int* in_sizes, int n_in,
                              void* d_out, int out_size) {
    const int*   idx   = (const int*)d_in[0];
    const int*   tgt   = (const int*)d_in[1];
    const float* emb   = (const float*)d_in[2];
    const float* Wq    = (const float*)d_in[3];
    const float* Wk    = (const float*)d_in[4];
    const float* Wv    = (const float*)d_in[5];
    const float* convq = (const float*)d_in[6];
    const float* convk = (const float*)d_in[7];
    const float* convv = (const float*)d_in[8];
    const float* Wb    = (const float*)d_in[9];
    const float* onw   = (const float*)d_in[10];
    const float* Wo    = (const float*)d_in[11];
    const float* anw   = (const float*)d_in[12];
    const float* mnw   = (const float*)d_in[13];
    const float* Wg    = (const float*)d_in[14];
    const float* Wu    = (const float*)d_in[15];
    const float* Wd    = (const float*)d_in[16];
    const float* fnw   = (const float*)d_in[17];
    const float* lmh   = (const float*)d_in[18];
    float* out = (float*)d_out;

    float *hb, *xb, *t0, *t1, *t2, *qb, *kb, *vb, *ob, *bb, *gb, *ub, *nl, *mk, *lfb;
    cudaGetSymbolAddress((void**)&hb,  g_h);
    cudaGetSymbolAddress((void**)&xb,  g_x);
    cudaGetSymbolAddress((void**)&t0,  g_t0);
    cudaGetSymbolAddress((void**)&t1,  g_t1);
    cudaGetSymbolAddress((void**)&t2,  g_t2);
    cudaGetSymbolAddress((void**)&qb,  g_q);
    cudaGetSymbolAddress((void**)&kb,  g_k);
    cudaGetSymbolAddress((void**)&vb,  g_v);
    cudaGetSymbolAddress((void**)&ob,  g_o);
    cudaGetSymbolAddress((void**)&bb,  g_beta);
    cudaGetSymbolAddress((void**)&gb,  g_gate);
    cudaGetSymbolAddress((void**)&ub,  g_up);
    cudaGetSymbolAddress((void**)&nl,  g_nll);
    cudaGetSymbolAddress((void**)&mk,  g_msk);
    cudaGetSymbolAddress((void**)&lfb, g_logits_fb);

    uint32_t *pAh, *pAl;
    uint32_t *wqh, *wql, *wkh, *wkl, *wvh, *wvl, *woh, *wol;
    uint32_t *wgh, *wgl, *wuh, *wul, *wdh, *wdl, *lmH, *lmL;
    cudaGetSymbolAddress((void**)&pAh, g_pA_h);
    cudaGetSymbolAddress((void**)&pAl, g_pA_l);
    cudaGetSymbolAddress((void**)&wqh, g_Wq_h); cudaGetSymbolAddress((void**)&wql, g_Wq_l);
    cudaGetSymbolAddress((void**)&wkh, g_Wk_h); cudaGetSymbolAddress((void**)&wkl, g_Wk_l);
    cudaGetSymbolAddress((void**)&wvh, g_Wv_h); cudaGetSymbolAddress((void**)&wvl, g_Wv_l);
    cudaGetSymbolAddress((void**)&woh, g_Wo_h); cudaGetSymbolAddress((void**)&wol, g_Wo_l);
    cudaGetSymbolAddress((void**)&wgh, g_Wg_h); cudaGetSymbolAddress((void**)&wgl, g_Wg_l);
    cudaGetSymbolAddress((void**)&wuh, g_Wu_h); cudaGetSymbolAddress((void**)&wul, g_Wu_l);
    cudaGetSymbolAddress((void**)&wdh, g_Wd_h); cudaGetSymbolAddress((void**)&wdl, g_Wd_l);
    cudaGetSymbolAddress((void**)&lmH, g_Lm_h); cudaGetSymbolAddress((void**)&lmL, g_Lm_l);

    const int SMEM4 = (4 * 1024 + 4096) * 2 * 4;  // 65536
    const int SMEM2 = (2 * 1024 + 4096) * 2 * 4;  // 49152
    cudaFuncSetAttribute(tbgemm_k<false, 4>, cudaFuncAttributeMaxDynamicSharedMemorySize, SMEM4);
    cudaFuncSetAttribute(tbgemm_k<true, 2>,  cudaFuncAttributeMaxDynamicSharedMemorySize, SMEM2);

    // ---- pack all weights (amortized over ~60 GEMM launches this call) ----
    pack_w_k<<<dim3(96, 1, LL), 256>>>(Wq, wqh, wql, 384, DD);
    pack_w_k<<<dim3(96, 1, LL), 256>>>(Wk, wkh, wkl, 384, DD);
    pack_w_k<<<dim3(96, 1, LL), 256>>>(Wv, wvh, wvl, 384, DD);
    pack_w_k<<<dim3(96, 1, LL), 256>>>(Wo, woh, wol, 384, DD);
    pack_w_k<<<dim3(192, 1, LL), 256>>>(Wg, wgh, wgl, 384, FFF);
    pack_w_k<<<dim3(192, 1, LL), 256>>>(Wu, wuh, wul, 384, FFF);
    pack_w_k<<<dim3(192, 1, LL), 256>>>(Wd, wdh, wdl, 1024, DD);
    pack_w_k<<<dim3(1024, 1, 1), 256>>>(lmh, lmH, lmL, 384, VV);

    const int ewarpBlocks = (TT * HH * 32 + 255) / 256;
    const int ffwBlocks = (TT * FFF / 2 + 255) / 256;

    embed_k<<<TT, 256>>>(idx, emb, hb);

    for (int l = 0; l < LL; l++) {
        const float* cq_l = convq + (size_t)l * DD * KC;
        const float* ck_l = convk + (size_t)l * DD * KC;
        const float* cv_l = convv + (size_t)l * DD * KC;
        const float* Wb_l = Wb + (size_t)l * DD * HH;
        const float* on_l = onw + (size_t)l * DKK;
        const float* an_l = anw + (size_t)l * DD;
        const float* mn_l = mnw + (size_t)l * DD;

        // attn rmsnorm -> fp32 xb (for beta) + packed A
        rmsnorm_pack_k<<<TT, 256>>>(hb, an_l, xb, pAh, pAl, DD);

        // QKV fused (z selects weight)
        dim3 gQKV(DD / 128, TT / 128, 3);
        tbgemm_k<false, 4><<<gQKV, 256, SMEM4>>>(
            pAh, pAl,
            wqh + (size_t)l * WSM, wql + (size_t)l * WSM,
            wkh + (size_t)l * WSM, wkl + (size_t)l * WSM,
            wvh + (size_t)l * WSM, wvl + (size_t)l * WSM,
            t0, t1, t2, TT, DD, DD);

        dim3 gPQ(TT, HH, 1);
        postqkv_k<<<gPQ, 64>>>(t0, t1, t2, cq_l, ck_l, cv_l, xb, Wb_l, qb, kb, vb, bb);

        delta_k<<<HH, 256>>>(qb, kb, vb, bb, ob);

        // per-head rmsnorm -> packed A
        headnorm_pack_k<<<ewarpBlocks, 256>>>(ob, on_l, pAh, pAl);

        // Wo (residual add), BM=64 for full-chip grid (192 blocks)
        dim3 gD(DD / 128, TT / 64, 1);
        tbgemm_k<true, 2><<<gD, 256, SMEM2>>>(
            pAh, pAl,
            woh + (size_t)l * WSM, wol + (size_t)l * WSM,
            woh + (size_t)l * WSM, wol + (size_t)l * WSM,
            woh + (size_t)l * WSM, wol + (size_t)l * WSM,
            hb, hb, hb, TT, DD, DD);

        // mlp rmsnorm -> packed A only
        rmsnorm_pack_k<<<TT, 256>>>(hb, mn_l, nullptr, pAh, pAl, DD);

        // gate + up fused
        dim3 gGU(FFF / 128, TT / 128, 2);
        tbgemm_k<false, 4><<<gGU, 256, SMEM4>>>(
            pAh, pAl,
            wgh + (size_t)l * WGU, wgl + (size_t)l * WGU,
            wuh + (size_t)l * WGU, wul + (size_t)l * WGU,
            wuh + (size_t)l * WGU, wul + (size_t)l * WGU,
            gb, ub, ub, TT, FFF, DD);

        // silu*up -> packed A
        silu_mul_pack_k<<<ffwBlocks, 256>>>(gb, ub, pAh, pAl);

        // down proj (residual add), BM=64
        tbgemm_k<true, 2><<<gD, 256, SMEM2>>>(
            pAh, pAl,
            wdh + (size_t)l * WDN, wdl + (size_t)l * WDN,
            wdh + (size_t)l * WDN, wdl + (size_t)l * WDN,
            wdh + (size_t)l * WDN, wdl + (size_t)l * WDN,
            hb, hb, hb, TT, DD, FFF);
    }

    rmsnorm_pack_k<<<TT, 256>>>(hb, fnw, nullptr, pAh, pAl, DD);

    const size_t LOGN = (size_t)TT * VV;
    float* logits = ((size_t)out_size >= LOGN) ? out : lfb;
    dim3 gV(VV / 128, TT / 128, 1);
    tbgemm_k<false, 4><<<gV, 256, SMEM4>>>(pAh, pAl, lmH, lmL, lmH, lmL, lmH, lmL,
                                           logits, logits, logits, TT, VV, DD);

    loss_rows_k<<<TT, 256>>>(logits, tgt, nl, mk);
    float* loss_dst = nullptr;
    if ((size_t)out_size >= LOGN + 1) loss_dst = out + LOGN;
    else if ((size_t)out_size < LOGN) loss_dst = out;
    if (loss_dst) loss_reduce_k<<<1, 256>>>(nl, mk, loss_dst);
}

// round 7
// speedup vs baseline: 2.7134x; 1.3506x over previous
#include <cuda_runtime.h>
#include <cuda_bf16.h>
#include <math.h>
#include <stdint.h>

// Problem constants
#define TT   2048
#define DD   768
#define HH   12
#define DKK  64
#define FFF  2048
#define VV   50304
#define LL   12
#define KC   4
#define EPSF 1e-6f
#define NCH  32     // chunks (T / 64)
#define PSTR 65     // padded smem stride

// packed word counts per matrix (word = uint32 = 2 bf16 packed along K)
#define WSM 294912     // 384*768   (Wq/Wk/Wv/Wo per layer)
#define WGU 786432     // 384*2048  (Wgate/Wup per layer)
#define WDN 786432     // 1024*768  (Wdown per layer)
#define WLM 19316736   // 384*50304 (lm_head)

// ---------------- scratch (__device__ globals; no allocation allowed) ----------------
__device__ float g_h[TT * DD];
__device__ float g_x[TT * DD];
__device__ float g_t0[TT * DD];
__device__ float g_t1[TT * DD];
__device__ float g_t2[TT * DD];
__device__ float g_q[TT * DD];
__device__ float g_k[TT * DD];
__device__ float g_v[TT * DD];
__device__ float g_o[TT * DD];
__device__ float g_beta[TT * HH];
__device__ float g_gate[TT * FFF];
__device__ float g_up[TT * FFF];
__device__ float g_nll[TT];
__device__ float g_msk[TT];
__device__ float g_logits_fb[(size_t)TT * VV];

// chunked-delta intermediates: [H][NCH][64][64]
__device__ float g_Qe[HH * NCH * 4096];
__device__ float g_Of[HH * NCH * 4096];
__device__ float g_Pm[HH * NCH * 4096];
__device__ float g_Rm[HH * NCH * 4096];

// packed activation A operand, max Kd=2048 -> 1024 words/row
__device__ uint32_t g_pA_h[TT * 1024];
__device__ uint32_t g_pA_l[TT * 1024];

// packed weights
__device__ uint32_t g_Wq_h[LL * WSM]; __device__ uint32_t g_Wq_l[LL * WSM];
__device__ uint32_t g_Wk_h[LL * WSM]; __device__ uint32_t g_Wk_l[LL * WSM];
__device__ uint32_t g_Wv_h[LL * WSM]; __device__ uint32_t g_Wv_l[LL * WSM];
__device__ uint32_t g_Wo_h[LL * WSM]; __device__ uint32_t g_Wo_l[LL * WSM];
__device__ uint32_t g_Wg_h[LL * WGU]; __device__ uint32_t g_Wg_l[LL * WGU];
__device__ uint32_t g_Wu_h[LL * WGU]; __device__ uint32_t g_Wu_l[LL * WGU];
__device__ uint32_t g_Wd_h[LL * WDN]; __device__ uint32_t g_Wd_l[LL * WDN];
__device__ uint32_t g_Lm_h[WLM];      __device__ uint32_t g_Lm_l[WLM];

// ---------------- helpers ----------------
__device__ __forceinline__ void mma_bf16(float* c, const uint32_t* a, const uint32_t* b) {
    asm volatile(
        "mma.sync.aligned.m16n8k16.row.col.f32.bf16.bf16.f32 "
        "{%0,%1,%2,%3}, {%4,%5,%6,%7}, {%8,%9}, {%0,%1,%2,%3};\n"
        : "+f"(c[0]), "+f"(c[1]), "+f"(c[2]), "+f"(c[3])
        : "r"(a[0]), "r"(a[1]), "r"(a[2]), "r"(a[3]), "r"(b[0]), "r"(b[1]));
}

__device__ __forceinline__ void split_pack(float x0, float x1, uint32_t& hp, uint32_t& lp) {
    __nv_bfloat16 h0 = __float2bfloat16(x0), h1 = __float2bfloat16(x1);
    float f0 = __bfloat162float(h0), f1 = __bfloat162float(h1);
    __nv_bfloat16 l0 = __float2bfloat16(x0 - f0), l1 = __float2bfloat16(x1 - f1);
    hp = (uint32_t)__bfloat16_as_ushort(h0) | ((uint32_t)__bfloat16_as_ushort(h1) << 16);
    lp = (uint32_t)__bfloat16_as_ushort(l0) | ((uint32_t)__bfloat16_as_ushort(l1) << 16);
}

// ---------------- kernels ----------------

__global__ void embed_k(const int* __restrict__ idx, const float* __restrict__ emb,
                        float* __restrict__ out) {
    int t = blockIdx.x;
    int row = idx[t];
    const float* src = emb + (size_t)row * DD;
    float* dst = out + (size_t)t * DD;
    for (int d = threadIdx.x; d < DD; d += blockDim.x) dst[d] = src[d];
}

// pack weights: src [count][2*Kw][N] fp32 -> dstH/dstL [count][Kw][N] words
__global__ void pack_w_k(const float* __restrict__ src, uint32_t* __restrict__ dH,
                         uint32_t* __restrict__ dL, int Kw, int N) {
    size_t nw = (size_t)Kw * N;
    size_t bs = (size_t)blockIdx.z * 2u * nw;
    size_t bd = (size_t)blockIdx.z * nw;
    for (size_t i = (size_t)blockIdx.x * blockDim.x + threadIdx.x; i < nw;
         i += (size_t)gridDim.x * blockDim.x) {
        size_t kw = i / N, n = i % N;
        float a0 = src[bs + (2 * kw) * N + n];
        float a1 = src[bs + (2 * kw + 1) * N + n];
        uint32_t h, l;
        split_pack(a0, a1, h, l);
        dH[bd + i] = h;
        dL[bd + i] = l;
    }
}

// rmsnorm; optional fp32 out; packed hi/lo words (row stride n/2)
__global__ void rmsnorm_pack_k(const float* __restrict__ in, const float* __restrict__ w,
                               float* __restrict__ outf,
                               uint32_t* __restrict__ pH, uint32_t* __restrict__ pL, int n) {
    int t = blockIdx.x;
    const float* r = in + (size_t)t * n;
    int tid = threadIdx.x;
    __shared__ float red[256];
    float s = 0.f;
    for (int i = tid; i < n; i += 256) { float vv = r[i]; s += vv * vv; }
    red[tid] = s; __syncthreads();
    for (int o = 128; o > 0; o >>= 1) { if (tid < o) red[tid] += red[tid + o]; __syncthreads(); }
    float rs = rsqrtf(red[0] / (float)n + EPSF);
    int nw = n >> 1;
    for (int i = tid; i < nw; i += 256) {
        float x0 = r[2 * i] * rs * w[2 * i];
        float x1 = r[2 * i + 1] * rs * w[2 * i + 1];
        if (outf) { outf[(size_t)t * n + 2 * i] = x0; outf[(size_t)t * n + 2 * i + 1] = x1; }
        uint32_t h, l;
        split_pack(x0, x1, h, l);
        pH[(size_t)t * nw + i] = h;
        pL[(size_t)t * nw + i] = l;
    }
}

// =======================================================================
// bf16x3 split-precision tensor-core GEMM with PRE-PACKED operands.
// (unchanged from round 5 — known good, ~mma.sync ceiling)
// =======================================================================
template <bool ADD, int MT>
__global__ __launch_bounds__(256) void tbgemm_k(
    const uint32_t* __restrict__ AHg, const uint32_t* __restrict__ ALg,
    const uint32_t* __restrict__ B0H, const uint32_t* __restrict__ B0L,
    const uint32_t* __restrict__ B1H, const uint32_t* __restrict__ B1L,
    const uint32_t* __restrict__ B2H, const uint32_t* __restrict__ B2L,
    float* __restrict__ C0, float* __restrict__ C1, float* __restrict__ C2,
    int M, int N, int Kd) {
    extern __shared__ uint32_t smw[];
    const int BM = MT * 32;
    const int AW = MT * 512;
    const int BUF = AW * 2 + 4096;
    const int Kw = Kd >> 1;
    (void)BM;

    const uint32_t* BHg = (blockIdx.z == 0) ? B0H : (blockIdx.z == 1 ? B1H : B2H);
    const uint32_t* BLg = (blockIdx.z == 0) ? B0L : (blockIdx.z == 1 ? B1L : B2L);
    float*          C   = (blockIdx.z == 0) ? C0  : (blockIdx.z == 1 ? C1  : C2);

    const int bm = blockIdx.y * (MT * 32), bn = blockIdx.x * 128;
    const int tid = threadIdx.x;
    const int warp = tid >> 5, lane = tid & 31;
    const int warpM = warp >> 2;
    const int warpN = warp & 3;
    const int g = lane >> 2, t4 = lane & 3;

    float acc[MT][4][4];
#pragma unroll
    for (int i = 0; i < MT; i++)
#pragma unroll
        for (int j = 0; j < 4; j++)
#pragma unroll
            for (int r = 0; r < 4; r++) acc[i][j][r] = 0.f;

    uint2 sa_h[MT], sa_l[MT];
    uint4 sb_h[2], sb_l[2];

    auto LOAD = [&](int kt) {
#pragma unroll
        for (int i = 0; i < MT; i++) {
            int id = i * 256 + tid;
            int r = id >> 3, c4 = id & 7;
            size_t off = (size_t)(bm + r) * Kw + kt * 16 + c4 * 2;
            sa_h[i] = *reinterpret_cast<const uint2*>(AHg + off);
            sa_l[i] = *reinterpret_cast<const uint2*>(ALg + off);
        }
#pragma unroll
        for (int i = 0; i < 2; i++) {
            int id = i * 256 + tid;
            int kw = id >> 5, n4 = id & 31;
            size_t off = (size_t)(kt * 16 + kw) * N + bn + n4 * 4;
            sb_h[i] = *reinterpret_cast<const uint4*>(BHg + off);
            sb_l[i] = *reinterpret_cast<const uint4*>(BLg + off);
        }
    };

    auto STORE = [&](int buf) {
        uint32_t* AH = smw + buf * BUF;
        uint32_t* AL = AH + AW;
        uint32_t* BH = AH + 2 * AW;
        uint32_t* BL = BH + 2048;
#pragma unroll
        for (int i = 0; i < MT; i++) {
            int id = i * 256 + tid;
            int r = id >> 3, c4 = id & 7;
            int off = r * 16 + ((c4 * 2) ^ ((r & 7) * 2));
            *reinterpret_cast<uint2*>(AH + off) = sa_h[i];
            *reinterpret_cast<uint2*>(AL + off) = sa_l[i];
        }
#pragma unroll
        for (int i = 0; i < 2; i++) {
            int id = i * 256 + tid;
            int kw = id >> 5, n4 = id & 31;
            int off = kw * 128 + ((n4 * 4) ^ ((kw * 8) & 127));
            *reinterpret_cast<uint4*>(BH + off) = sb_h[i];
            *reinterpret_cast<uint4*>(BL + off) = sb_l[i];
        }
    };

    auto COMPUTE = [&](int buf) {
        uint32_t* AH = smw + buf * BUF;
        uint32_t* AL = AH + AW;
        uint32_t* BH = AH + 2 * AW;
        uint32_t* BL = BH + 2048;
#pragma unroll
        for (int ks = 0; ks < 2; ks++) {
            uint32_t ah[MT][4], al[MT][4];
#pragma unroll
            for (int mt = 0; mt < MT; mt++) {
                int r0 = warpM * (MT * 16) + mt * 16 + g;
                int r1 = r0 + 8;
                int ka = ks * 8 + t4, kb = ka + 4;
                int o0 = r0 * 16 + (ka ^ ((r0 & 7) * 2));
                int o1 = r1 * 16 + (ka ^ ((r1 & 7) * 2));
                int o2 = r0 * 16 + (kb ^ ((r0 & 7) * 2));
                int o3 = r1 * 16 + (kb ^ ((r1 & 7) * 2));
                ah[mt][0] = AH[o0]; ah[mt][1] = AH[o1]; ah[mt][2] = AH[o2]; ah[mt][3] = AH[o3];
                al[mt][0] = AL[o0]; al[mt][1] = AL[o1]; al[mt][2] = AL[o2]; al[mt][3] = AL[o3];
            }
            uint32_t bh[4][2], bl[4][2];
#pragma unroll
            for (int nt = 0; nt < 4; nt++) {
                int n = warpN * 32 + nt * 8 + g;
                int k0w = ks * 8 + t4, k1w = k0w + 4;
                int o0 = k0w * 128 + (n ^ ((k0w * 8) & 127));
                int o1 = k1w * 128 + (n ^ ((k1w * 8) & 127));
                bh[nt][0] = BH[o0]; bh[nt][1] = BH[o1];
                bl[nt][0] = BL[o0]; bl[nt][1] = BL[o1];
            }
#pragma unroll
            for (int mt = 0; mt < MT; mt++)
#pragma unroll
                for (int nt = 0; nt < 4; nt++) {
                    mma_bf16(acc[mt][nt], al[mt], bh[nt]);
                    mma_bf16(acc[mt][nt], ah[mt], bl[nt]);
                    mma_bf16(acc[mt][nt], ah[mt], bh[nt]);
                }
        }
    };

    const int ntiles = Kd / 32;
    LOAD(0);
    STORE(0);
    __syncthreads();
    for (int kt = 0; kt < ntiles; kt++) {
        if (kt + 1 < ntiles) LOAD(kt + 1);
        COMPUTE(kt & 1);
        if (kt + 1 < ntiles) STORE((kt + 1) & 1);
        __syncthreads();
    }

#pragma unroll
    for (int mt = 0; mt < MT; mt++) {
        int r0 = bm + warpM * (MT * 16) + mt * 16 + g;
#pragma unroll
        for (int nt = 0; nt < 4; nt++) {
            int c0 = bn + warpN * 32 + nt * 8 + 2 * t4;
            float* p0 = C + (size_t)r0 * N + c0;
            float* p1 = C + (size_t)(r0 + 8) * N + c0;
            if (ADD) {
                p0[0] += acc[mt][nt][0]; p0[1] += acc[mt][nt][1];
                p1[0] += acc[mt][nt][2]; p1[1] += acc[mt][nt][3];
            } else {
                p0[0] = acc[mt][nt][0]; p0[1] = acc[mt][nt][1];
                p1[0] = acc[mt][nt][2]; p1[1] = acc[mt][nt][3];
            }
        }
    }
}

// Fused post-QKV: conv(K=4)+SiLU q,k,v; l2norm q,k; beta. block (t,h), 64 thr.
__global__ __launch_bounds__(64) void postqkv_k(
    const float* __restrict__ t0, const float* __restrict__ t1, const float* __restrict__ t2,
    const float* __restrict__ cq, const float* __restrict__ ck, const float* __restrict__ cv,
    const float* __restrict__ x, const float* __restrict__ Wb,
    float* __restrict__ q, float* __restrict__ k, float* __restrict__ v,
    float* __restrict__ beta) {
    int t = blockIdx.x, h = blockIdx.y;
    int tid = threadIdx.x;
    int d = h * 64 + tid;
    int wrp = tid >> 5, lane = tid & 31;

    auto conv = [&](const float* src, const float* w) -> float {
        float acc = 0.f;
#pragma unroll
        for (int j = 0; j < KC; j++) {
            int tt = t - (KC - 1) + j;
            if (tt >= 0) acc += src[(size_t)tt * DD + d] * w[d * KC + j];
        }
        return acc / (1.f + expf(-acc));
    };
    float qv = conv(t0, cq);
    float kv = conv(t1, ck);
    float vv = conv(t2, cv);

    float sq = qv * qv, sk = kv * kv;
    float sb = 0.f;
    const float* xr = x + (size_t)t * DD;
    for (int i = tid; i < DD; i += 64) sb += xr[i] * Wb[i * HH + h];
#pragma unroll
    for (int o = 16; o > 0; o >>= 1) {
        sq += __shfl_xor_sync(0xffffffffu, sq, o);
        sk += __shfl_xor_sync(0xffffffffu, sk, o);
        sb += __shfl_xor_sync(0xffffffffu, sb, o);
    }
    __shared__ float red[3][2];
    if (lane == 0) { red[0][wrp] = sq; red[1][wrp] = sk; red[2][wrp] = sb; }
    __syncthreads();
    float rq = rsqrtf(red[0][0] + red[0][1] + EPSF);
    float rk = rsqrtf(red[1][0] + red[1][1] + EPSF);
    size_t gi = (size_t)t * DD + d;
    q[gi] = qv * rq;
    k[gi] = kv * rk;
    v[gi] = vv;
    if (tid == 0) beta[t * HH + h] = 1.f / (1.f + expf(-(red[2][0] + red[2][1])));
}

// =======================================================================
// Chunked delta rule, phase 1 (PARALLEL over 32 chunks x 12 heads).
// Per (c,h): A = stril(diag(b)KK^T); T = (I+A)^-1; W = T(bK); U0 = T(bV);
// G = tril(QK^T); Qeff = Q - GW; Ofix = G U0; P = K^T W; R = K^T U0.
// Exactly equivalent to the step recurrence (WY form).
// =======================================================================
__global__ __launch_bounds__(256) void deltaprep_k(
    const float* __restrict__ q, const float* __restrict__ k,
    const float* __restrict__ v, const float* __restrict__ beta,
    float* __restrict__ Qe, float* __restrict__ Of,
    float* __restrict__ Pm, float* __restrict__ Rm) {
    extern __shared__ float sm[];
    float* sK = sm;
    float* sV = sK + 64 * PSTR;
    float* sQ = sV + 64 * PSTR;
    float* bA = sQ + 64 * PSTR;   // A, later W
    float* bT = bA + 64 * PSTR;   // T, later G
    float* bU = bT + 64 * PSTR;   // U0
    float* sb = bU + 64 * PSTR;   // beta [64]
    const int c = blockIdx.x, h = blockIdx.y;
    const int tid = threadIdx.x;
    const int tr = (tid >> 4) * 4, tc = (tid & 15) * 4;

    for (int i = tid; i < 4096; i += 256) {
        int t = i >> 6, d = i & 63;
        size_t g = (size_t)(c * 64 + t) * DD + h * 64 + d;
        sK[t * PSTR + d] = k[g];
        sV[t * PSTR + d] = v[g];
        sQ[t * PSTR + d] = q[g];
    }
    if (tid < 64) sb[tid] = beta[(c * 64 + tid) * HH + h];
    __syncthreads();

    // A = stril(diag(beta) K K^T)  (zeros on/above diag)
    {
        float acc[4][4] = {};
        for (int m = 0; m < 64; m++) {
            float a[4], b[4];
#pragma unroll
            for (int i = 0; i < 4; i++) a[i] = sK[(tr + i) * PSTR + m];
#pragma unroll
            for (int j = 0; j < 4; j++) b[j] = sK[(tc + j) * PSTR + m];
#pragma unroll
            for (int i = 0; i < 4; i++)
#pragma unroll
                for (int j = 0; j < 4; j++) acc[i][j] += a[i] * b[j];
        }
#pragma unroll
        for (int i = 0; i < 4; i++)
#pragma unroll
            for (int j = 0; j < 4; j++) {
                int t = tr + i, s = tc + j;
                bA[t * PSTR + s] = (s < t) ? acc[i][j] * sb[t] : 0.f;
            }
    }
    __syncthreads();

    // T = (I + A)^{-1}: forward substitution; threads 0..63 own columns.
    // T is lower-triangular (zeros above diag emerge naturally).
    for (int t = 0; t < 64; t++) {
        if (tid < 64) {
            float acc = (t == tid) ? 1.f : 0.f;
            for (int s = 0; s < t; s++) acc -= bA[t * PSTR + s] * bT[s * PSTR + tid];
            bT[t * PSTR + tid] = acc;
        }
        __syncthreads();
    }

    // W = T (beta K) and U0 = T (beta V)
    {
        float accW[4][4] = {}, accU[4][4] = {};
        for (int m = 0; m < 64; m++) {
            float a[4];
#pragma unroll
            for (int i = 0; i < 4; i++) a[i] = bT[(tr + i) * PSTR + m] * sb[m];
            float bk[4], bv[4];
#pragma unroll
            for (int j = 0; j < 4; j++) {
                bk[j] = sK[m * PSTR + tc + j];
                bv[j] = sV[m * PSTR + tc + j];
            }
#pragma unroll
            for (int i = 0; i < 4; i++)
#pragma unroll
                for (int j = 0; j < 4; j++) {
                    accW[i][j] += a[i] * bk[j];
                    accU[i][j] += a[i] * bv[j];
                }
        }
        __syncthreads();  // all reads of A done before overwriting bA with W
#pragma unroll
        for (int i = 0; i < 4; i++)
#pragma unroll
            for (int j = 0; j < 4; j++) {
                bA[(tr + i) * PSTR + tc + j] = accW[i][j];
                bU[(tr + i) * PSTR + tc + j] = accU[i][j];
            }
    }
    __syncthreads();

    // G = tril(Q K^T) including diagonal -> bT (T no longer needed)
    {
        float acc[4][4] = {};
        for (int m = 0; m < 64; m++) {
            float a[4], b[4];
#pragma unroll
            for (int i = 0; i < 4; i++) a[i] = sQ[(tr + i) * PSTR + m];
#pragma unroll
            for (int j = 0; j < 4; j++) b[j] = sK[(tc + j) * PSTR + m];
#pragma unroll
            for (int i = 0; i < 4; i++)
#pragma unroll
                for (int j = 0; j < 4; j++) acc[i][j] += a[i] * b[j];
        }
        __syncthreads();  // W/U0 phase reads of bT done
#pragma unroll
        for (int i = 0; i < 4; i++)
#pragma unroll
            for (int j = 0; j < 4; j++) {
                int t = tr + i, s = tc + j;
                bT[t * PSTR + s] = (s <= t) ? acc[i][j] : 0.f;
            }
    }
    __syncthreads();

    const size_t base = ((size_t)(h * NCH + c)) << 12;

    // Qeff = Q - G W ; Ofix = G U0
    {
        float accQ[4][4] = {}, accO[4][4] = {};
        for (int m = 0; m < 64; m++) {
            float a[4];
#pragma unroll
            for (int i = 0; i < 4; i++) a[i] = bT[(tr + i) * PSTR + m];
            float bw[4], bu[4];
#pragma unroll
            for (int j = 0; j < 4; j++) {
                bw[j] = bA[m * PSTR + tc + j];
                bu[j] = bU[m * PSTR + tc + j];
            }
#pragma unroll
            for (int i = 0; i < 4; i++)
#pragma unroll
                for (int j = 0; j < 4; j++) {
                    accQ[i][j] += a[i] * bw[j];
                    accO[i][j] += a[i] * bu[j];
                }
        }
#pragma unroll
        for (int i = 0; i < 4; i++)
#pragma unroll
            for (int j = 0; j < 4; j++) {
                Qe[base + (tr + i) * 64 + tc + j] =
                    sQ[(tr + i) * PSTR + tc + j] - accQ[i][j];
                Of[base + (tr + i) * 64 + tc + j] = accO[i][j];
            }
    }

    // P = K^T W ; R = K^T U0
    {
        float accP[4][4] = {}, accR[4][4] = {};
        for (int m = 0; m < 64; m++) {
            float a[4];
#pragma unroll
            for (int i = 0; i < 4; i++) a[i] = sK[m * PSTR + tr + i];
            float bw[4], bu[4];
#pragma unroll
            for (int j = 0; j < 4; j++) {
                bw[j] = bA[m * PSTR + tc + j];
                bu[j] = bU[m * PSTR + tc + j];
            }
#pragma unroll
            for (int i = 0; i < 4; i++)
#pragma unroll
                for (int j = 0; j < 4; j++) {
                    accP[i][j] += a[i] * bw[j];
                    accR[i][j] += a[i] * bu[j];
                }
        }
#pragma unroll
        for (int i = 0; i < 4; i++)
#pragma unroll
            for (int j = 0; j < 4; j++) {
                Pm[base + (tr + i) * 64 + tc + j] = accP[i][j];
                Rm[base + (tr + i) * 64 + tc + j] = accR[i][j];
            }
    }
}

// =======================================================================
// Chunked delta rule, phase 2 (SCAN). grid (HH, 8): head x 8-col group.
// Per chunk: O_c = Qeff_c S + Ofix_c ; S <- S - P_c S + R_c.
// S columns independent -> 96 blocks.
// =======================================================================
__global__ __launch_bounds__(256) void deltascan_k(
    const float* __restrict__ Qe, const float* __restrict__ Of,
    const float* __restrict__ Pm, const float* __restrict__ Rm,
    float* __restrict__ o) {
    const int h = blockIdx.x, cg = blockIdx.y;
    const int tid = threadIdx.x;
    __shared__ float sQe[64 * PSTR], sP[64 * PSTR];
    __shared__ float S[64 * 9], sOf[512], sR[512];

    for (int i = tid; i < 64 * 9; i += 256) S[i] = 0.f;
    __syncthreads();

#pragma unroll 1
    for (int c = 0; c < NCH; c++) {
        size_t base = ((size_t)(h * NCH + c)) << 12;
        for (int i = tid; i < 4096; i += 256) {
            int t = i >> 6, d = i & 63;
            sQe[t * PSTR + d] = Qe[base + i];
            sP[t * PSTR + d] = Pm[base + i];
        }
        for (int i = tid; i < 512; i += 256) {
            int t = i >> 3, j = i & 7;
            sOf[i] = Of[base + t * 64 + cg * 8 + j];
            sR[i] = Rm[base + t * 64 + cg * 8 + j];
        }
        __syncthreads();

        float outv[2], ns[2];
#pragma unroll
        for (int u = 0; u < 2; u++) {
            int idx = tid + u * 256;
            int t = idx >> 3, j = idx & 7;
            float a1 = sOf[idx];
            float a2 = S[t * 9 + j] + sR[idx];
#pragma unroll
            for (int m = 0; m < 64; m++) {
                float sv = S[m * 9 + j];
                a1 += sQe[t * PSTR + m] * sv;
                a2 -= sP[t * PSTR + m] * sv;
            }
            outv[u] = a1;
            ns[u] = a2;
        }
#pragma unroll
        for (int u = 0; u < 2; u++) {
            int idx = tid + u * 256;
            int t = idx >> 3, j = idx & 7;
            o[(size_t)(c * 64 + t) * DD + h * 64 + cg * 8 + j] = outv[u];
        }
        __syncthreads();
#pragma unroll
        for (int u = 0; u < 2; u++) {
            int idx = tid + u * 256;
            int t = idx >> 3, j = idx & 7;
            S[t * 9 + j] = ns[u];
        }
        __syncthreads();
    }
}

// per-64 rmsnorm * w of delta output -> packed words (feeds Wo GEMM)
__global__ void headnorm_pack_k(const float* __restrict__ o, const float* __restrict__ w,
                                uint32_t* __restrict__ pH, uint32_t* __restrict__ pL) {
    int gw = (blockIdx.x * blockDim.x + threadIdx.x) >> 5;
    int lane = threadIdx.x & 31;
    if (gw >= TT * HH) return;
    const float* r = o + (size_t)gw * 64;
    float a = r[2 * lane], b = r[2 * lane + 1];
    float s = a * a + b * b;
#pragma unroll
    for (int os = 16; os > 0; os >>= 1) s += __shfl_xor_sync(0xffffffffu, s, os);
    float rs = rsqrtf(s * (1.f / 64.f) + EPSF);
    int t = gw / HH, h = gw % HH;
    uint32_t hw, lw;
    split_pack(a * rs * w[2 * lane], b * rs * w[2 * lane + 1], hw, lw);
    size_t wi = (size_t)t * 384 + h * 32 + lane;
    pH[wi] = hw;
    pL[wi] = lw;
}

// silu(g)*u, writes packed words; i indexes element pairs
__global__ void silu_mul_pack_k(const float* __restrict__ g, const float* __restrict__ u,
                                uint32_t* __restrict__ pH, uint32_t* __restrict__ pL) {
    int i = blockIdx.x * blockDim.x + threadIdx.x;
    if (i >= TT * FFF / 2) return;
    float g0 = g[2 * i], g1 = g[2 * i + 1];
    float y0 = (g0 / (1.f + expf(-g0))) * u[2 * i];
    float y1 = (g1 / (1.f + expf(-g1))) * u[2 * i + 1];
    uint32_t h, l;
    split_pack(y0, y1, h, l);
    pH[i] = h;
    pL[i] = l;
}

__global__ void loss_rows_k(const float* __restrict__ logits, const int* __restrict__ tgt,
                            float* __restrict__ nll, float* __restrict__ msk) {
    int t = blockIdx.x;
    const float* r = logits + (size_t)t * VV;
    int tid = threadIdx.x;
    __shared__ float red[256];
    float m = -INFINITY;
    for (int i = tid; i < VV; i += 256) m = fmaxf(m, r[i]);
    red[tid] = m; __syncthreads();
    for (int o = 128; o > 0; o >>= 1) { if (tid < o) red[tid] = fmaxf(red[tid], red[tid + o]); __syncthreads(); }
    float rowmax = red[0]; __syncthreads();
    float s = 0.f;
    for (int i = tid; i < VV; i += 256) s += expf(r[i] - rowmax);
    red[tid] = s; __syncthreads();
    for (int o = 128; o > 0; o >>= 1) { if (tid < o) red[tid] += red[tid + o]; __syncthreads(); }
    if (tid == 0) {
        float denom = red[0];
        int tg = tgt[t];
        float mask = (tg >= 0) ? 1.f : 0.f;
        int tc = tg < 0 ? 0 : (tg > VV - 1 ? VV - 1 : tg);
        float lp = r[tc] - rowmax - logf(denom);
        nll[t] = -lp * mask;
        msk[t] = mask;
    }
}

__global__ void loss_reduce_k(const float* __restrict__ nll, const float* __restrict__ msk,
                              float* __restrict__ out) {
    int tid = threadIdx.x;
    __shared__ float r1[256], r2[256];
    float s = 0.f, c = 0.f;
    for (int i = tid; i < TT; i += 256) { s += nll[i]; c += msk[i]; }
    r1[tid] = s; r2[tid] = c; __syncthreads();
    for (int o = 128; o > 0; o >>= 1) {
        if (tid < o) { r1[tid] += r1[tid + o]; r2[tid] += r2[tid + o]; }
        __syncthreads();
    }
    if (tid == 0) out[0] = r1[0] / fmaxf(r2[0], 1.f);
}

// ---------------- host launcher ----------------
extern "C" void kernel_launch(void* const* d_in, const int* in_sizes, int n_in,
                              void* d_out, int out_size) {
    const int*   idx   = (const int*)d_in[0];
    const int*   tgt   = (const int*)d_in[1];
    const float* emb   = (const float*)d_in[2];
    const float* Wq    = (const float*)d_in[3];
    const float* Wk    = (const float*)d_in[4];
    const float* Wv    = (const float*)d_in[5];
    const float* convq = (const float*)d_in[6];
    const float* convk = (const float*)d_in[7];
    const float* convv = (const float*)d_in[8];
    const float* Wb    = (const float*)d_in[9];
    const float* onw   = (const float*)d_in[10];
    const float* Wo    = (const float*)d_in[11];
    const float* anw   = (const float*)d_in[12];
    const float* mnw   = (const float*)d_in[13];
    const float* Wg    = (const float*)d_in[14];
    const float* Wu    = (const float*)d_in[15];
    const float* Wd    = (const float*)d_in[16];
    const float* fnw   = (const float*)d_in[17];
    const float* lmh   = (const float*)d_in[18];
    float* out = (float*)d_out;

    float *hb, *xb, *t0, *t1, *t2, *qb, *kb, *vb, *ob, *bb, *gb, *ub, *nl, *mk, *lfb;
    cudaGetSymbolAddress((void**)&hb,  g_h);
    cudaGetSymbolAddress((void**)&xb,  g_x);
    cudaGetSymbolAddress((void**)&t0,  g_t0);
    cudaGetSymbolAddress((void**)&t1,  g_t1);
    cudaGetSymbolAddress((void**)&t2,  g_t2);
    cudaGetSymbolAddress((void**)&qb,  g_q);
    cudaGetSymbolAddress((void**)&kb,  g_k);
    cudaGetSymbolAddress((void**)&vb,  g_v);
    cudaGetSymbolAddress((void**)&ob,  g_o);
    cudaGetSymbolAddress((void**)&bb,  g_beta);
    cudaGetSymbolAddress((void**)&gb,  g_gate);
    cudaGetSymbolAddress((void**)&ub,  g_up);
    cudaGetSymbolAddress((void**)&nl,  g_nll);
    cudaGetSymbolAddress((void**)&mk,  g_msk);
    cudaGetSymbolAddress((void**)&lfb, g_logits_fb);

    float *dQe, *dOf, *dPm, *dRm;
    cudaGetSymbolAddress((void**)&dQe, g_Qe);
    cudaGetSymbolAddress((void**)&dOf, g_Of);
    cudaGetSymbolAddress((void**)&dPm, g_Pm);
    cudaGetSymbolAddress((void**)&dRm, g_Rm);

    uint32_t *pAh, *pAl;
    uint32_t *wqh, *wql, *wkh, *wkl, *wvh, *wvl, *woh, *wol;
    uint32_t *wgh, *wgl, *wuh, *wul, *wdh, *wdl, *lmH, *lmL;
    cudaGetSymbolAddress((void**)&pAh, g_pA_h);
    cudaGetSymbolAddress((void**)&pAl, g_pA_l);
    cudaGetSymbolAddress((void**)&wqh, g_Wq_h); cudaGetSymbolAddress((void**)&wql, g_Wq_l);
    cudaGetSymbolAddress((void**)&wkh, g_Wk_h); cudaGetSymbolAddress((void**)&wkl, g_Wk_l);
    cudaGetSymbolAddress((void**)&wvh, g_Wv_h); cudaGetSymbolAddress((void**)&wvl, g_Wv_l);
    cudaGetSymbolAddress((void**)&woh, g_Wo_h); cudaGetSymbolAddress((void**)&wol, g_Wo_l);
    cudaGetSymbolAddress((void**)&wgh, g_Wg_h); cudaGetSymbolAddress((void**)&wgl, g_Wg_l);
    cudaGetSymbolAddress((void**)&wuh, g_Wu_h); cudaGetSymbolAddress((void**)&wul, g_Wu_l);
    cudaGetSymbolAddress((void**)&wdh, g_Wd_h); cudaGetSymbolAddress((void**)&wdl, g_Wd_l);
    cudaGetSymbolAddress((void**)&lmH, g_Lm_h); cudaGetSymbolAddress((void**)&lmL, g_Lm_l);

    const int SMEM4 = (4 * 1024 + 4096) * 2 * 4;  // 65536
    const int SMEM2 = (2 * 1024 + 4096) * 2 * 4;  // 49152
    const int PREPSM = (6 * 64 * PSTR + 64) * 4 + 256;  // ~100 KB
    cudaFuncSetAttribute(tbgemm_k<false, 4>, cudaFuncAttributeMaxDynamicSharedMemorySize, SMEM4);
    cudaFuncSetAttribute(tbgemm_k<true, 2>,  cudaFuncAttributeMaxDynamicSharedMemorySize, SMEM2);
    cudaFuncSetAttribute(deltaprep_k, cudaFuncAttributeMaxDynamicSharedMemorySize, PREPSM);

    // ---- pack all weights ----
    pack_w_k<<<dim3(96, 1, LL), 256>>>(Wq, wqh, wql, 384, DD);
    pack_w_k<<<dim3(96, 1, LL), 256>>>(Wk, wkh, wkl, 384, DD);
    pack_w_k<<<dim3(96, 1, LL), 256>>>(Wv, wvh, wvl, 384, DD);
    pack_w_k<<<dim3(96, 1, LL), 256>>>(Wo, woh, wol, 384, DD);
    pack_w_k<<<dim3(192, 1, LL), 256>>>(Wg, wgh, wgl, 384, FFF);
    pack_w_k<<<dim3(192, 1, LL), 256>>>(Wu, wuh, wul, 384, FFF);
    pack_w_k<<<dim3(192, 1, LL), 256>>>(Wd, wdh, wdl, 1024, DD);
    pack_w_k<<<dim3(1024, 1, 1), 256>>>(lmh, lmH, lmL, 384, VV);

    const int ewarpBlocks = (TT * HH * 32 + 255) / 256;
    const int ffwBlocks = (TT * FFF / 2 + 255) / 256;

    embed_k<<<TT, 256>>>(idx, emb, hb);

    for (int l = 0; l < LL; l++) {
        const float* cq_l = convq + (size_t)l * DD * KC;
        const float* ck_l = convk + (size_t)l * DD * KC;
        const float* cv_l = convv + (size_t)l * DD * KC;
        const float* Wb_l = Wb + (size_t)l * DD * HH;
        const float* on_l = onw + (size_t)l * DKK;
        const float* an_l = anw + (size_t)l * DD;
        const float* mn_l = mnw + (size_t)l * DD;

        rmsnorm_pack_k<<<TT, 256>>>(hb, an_l, xb, pAh, pAl, DD);

        dim3 gQKV(DD / 128, TT / 128, 3);
        tbgemm_k<false, 4><<<gQKV, 256, SMEM4>>>(
            pAh, pAl,
            wqh + (size_t)l * WSM, wql + (size_t)l * WSM,
            wkh + (size_t)l * WSM, wkl + (size_t)l * WSM,
            wvh + (size_t)l * WSM, wvl + (size_t)l * WSM,
            t0, t1, t2, TT, DD, DD);

        dim3 gPQ(TT, HH, 1);
        postqkv_k<<<gPQ, 64>>>(t0, t1, t2, cq_l, ck_l, cv_l, xb, Wb_l, qb, kb, vb, bb);

        // chunked delta rule: parallel prep + short scan
        deltaprep_k<<<dim3(NCH, HH), 256, PREPSM>>>(qb, kb, vb, bb, dQe, dOf, dPm, dRm);
        deltascan_k<<<dim3(HH, 8), 256>>>(dQe, dOf, dPm, dRm, ob);

        headnorm_pack_k<<<ewarpBlocks, 256>>>(ob, on_l, pAh, pAl);

        dim3 gD(DD / 128, TT / 64, 1);
        tbgemm_k<true, 2><<<gD, 256, SMEM2>>>(
            pAh, pAl,
            woh + (size_t)l * WSM, wol + (size_t)l * WSM,
            woh + (size_t)l * WSM, wol + (size_t)l * WSM,
            woh + (size_t)l * WSM, wol + (size_t)l * WSM,
            hb, hb, hb, TT, DD, DD);

        rmsnorm_pack_k<<<TT, 256>>>(hb, mn_l, nullptr, pAh, pAl, DD);

        dim3 gGU(FFF / 128, TT / 128, 2);
        tbgemm_k<false, 4><<<gGU, 256, SMEM4>>>(
            pAh, pAl,
            wgh + (size_t)l * WGU, wgl + (size_t)l * WGU,
            wuh + (size_t)l * WGU, wul + (size_t)l * WGU,
            wuh + (size_t)l * WGU, wul + (size_t)l * WGU,
            gb, ub, ub, TT, FFF, DD);

        silu_mul_pack_k<<<ffwBlocks, 256>>>(gb, ub, pAh, pAl);

        tbgemm_k<true, 2><<<gD, 256, SMEM2>>>(
            pAh, pAl,
            wdh + (size_t)l * WDN, wdl + (size_t)l * WDN,
            wdh + (size_t)l * WDN, wdl + (size_t)l * WDN,
            wdh + (size_t)l * WDN, wdl + (size_t)l * WDN,
            hb, hb, hb, TT, DD, FFF);
    }

    rmsnorm_pack_k<<<TT, 256>>>(hb, fnw, nullptr, pAh, pAl, DD);

    const size_t LOGN = (size_t)TT * VV;
    float* logits = ((size_t)out_size >= LOGN) ? out : lfb;
    dim3 gV(VV / 128, TT / 128, 1);
    tbgemm_k<false, 4><<<gV, 256, SMEM4>>>(pAh, pAl, lmH, lmL, lmH, lmL, lmH, lmL,
                                           logits, logits, logits, TT, VV, DD);

    loss_rows_k<<<TT, 256>>>(logits, tgt, nl, mk);
    float* loss_dst = nullptr;
    if ((size_t)out_size >= LOGN + 1) loss_dst = out + LOGN;
    else if ((size_t)out_size < LOGN) loss_dst = out;
    if (loss_dst) loss_reduce_k<<<1, 256>>>(nl, mk, loss_dst);
}

// round 8
// speedup vs baseline: 2.8843x; 1.0630x over previous
#include <cuda_runtime.h>
#include <cuda_bf16.h>
#include <math.h>
#include <stdint.h>

// Problem constants
#define TT   2048
#define DD   768
#define HH   12
#define DKK  64
#define FFF  2048
#define VV   50304
#define LL   12
#define KC   4
#define EPSF 1e-6f
#define NCH  32     // chunks (T / 64)
#define PSTR 65     // padded smem stride

// packed word counts per matrix (word = uint32 = 2 bf16 packed along K)
#define WSM 294912     // 384*768   (Wq/Wk/Wv/Wo per layer)
#define WGU 786432     // 384*2048  (Wgate/Wup per layer)
#define WDN 786432     // 1024*768  (Wdown per layer)
#define WLM 19316736   // 384*50304 (lm_head)

// ---------------- scratch (__device__ globals; no allocation allowed) ----------------
__device__ float g_h[TT * DD];
__device__ float g_x[TT * DD];
__device__ float g_t0[TT * DD];
__device__ float g_t1[TT * DD];
__device__ float g_t2[TT * DD];
__device__ float g_q[TT * DD];
__device__ float g_k[TT * DD];
__device__ float g_v[TT * DD];
__device__ float g_o[TT * DD];
__device__ float g_beta[TT * HH];
__device__ float g_gate[TT * FFF];
__device__ float g_up[TT * FFF];
__device__ float g_nll[TT];
__device__ float g_msk[TT];
__device__ float g_logits_fb[(size_t)TT * VV];

// chunked-delta intermediates: [H][NCH][64][64]
__device__ float g_Qe[HH * NCH * 4096];
__device__ float g_Of[HH * NCH * 4096];
__device__ float g_Pm[HH * NCH * 4096];
__device__ float g_Rm[HH * NCH * 4096];

// packed activation A operand, max Kd=2048 -> 1024 words/row
__device__ uint32_t g_pA_h[TT * 1024];
__device__ uint32_t g_pA_l[TT * 1024];

// packed weights
__device__ uint32_t g_Wq_h[LL * WSM]; __device__ uint32_t g_Wq_l[LL * WSM];
__device__ uint32_t g_Wk_h[LL * WSM]; __device__ uint32_t g_Wk_l[LL * WSM];
__device__ uint32_t g_Wv_h[LL * WSM]; __device__ uint32_t g_Wv_l[LL * WSM];
__device__ uint32_t g_Wo_h[LL * WSM]; __device__ uint32_t g_Wo_l[LL * WSM];
__device__ uint32_t g_Wg_h[LL * WGU]; __device__ uint32_t g_Wg_l[LL * WGU];
__device__ uint32_t g_Wu_h[LL * WGU]; __device__ uint32_t g_Wu_l[LL * WGU];
__device__ uint32_t g_Wd_h[LL * WDN]; __device__ uint32_t g_Wd_l[LL * WDN];
__device__ uint32_t g_Lm_h[WLM];      __device__ uint32_t g_Lm_l[WLM];

// ---------------- helpers ----------------
__device__ __forceinline__ void mma_bf16(float* c, const uint32_t* a, const uint32_t* b) {
    asm volatile(
        "mma.sync.aligned.m16n8k16.row.col.f32.bf16.bf16.f32 "
        "{%0,%1,%2,%3}, {%4,%5,%6,%7}, {%8,%9}, {%0,%1,%2,%3};\n"
        : "+f"(c[0]), "+f"(c[1]), "+f"(c[2]), "+f"(c[3])
        : "r"(a[0]), "r"(a[1]), "r"(a[2]), "r"(a[3]), "r"(b[0]), "r"(b[1]));
}

__device__ __forceinline__ void split_pack(float x0, float x1, uint32_t& hp, uint32_t& lp) {
    __nv_bfloat16 h0 = __float2bfloat16(x0), h1 = __float2bfloat16(x1);
    float f0 = __bfloat162float(h0), f1 = __bfloat162float(h1);
    __nv_bfloat16 l0 = __float2bfloat16(x0 - f0), l1 = __float2bfloat16(x1 - f1);
    hp = (uint32_t)__bfloat16_as_ushort(h0) | ((uint32_t)__bfloat16_as_ushort(h1) << 16);
    lp = (uint32_t)__bfloat16_as_ushort(l0) | ((uint32_t)__bfloat16_as_ushort(l1) << 16);
}

// ---------------- kernels ----------------

__global__ void embed_k(const int* __restrict__ idx, const float* __restrict__ emb,
                        float* __restrict__ out) {
    int t = blockIdx.x;
    int row = idx[t];
    const float* src = emb + (size_t)row * DD;
    float* dst = out + (size_t)t * DD;
    for (int d = threadIdx.x; d < DD; d += blockDim.x) dst[d] = src[d];
}

// pack weights: src [count][2*Kw][N] fp32 -> dstH/dstL [count][Kw][N] words.
// grid: (ceil(N/256), Kw, count) -- no integer division in the hot path.
__global__ void pack_w_k(const float* __restrict__ src, uint32_t* __restrict__ dH,
                         uint32_t* __restrict__ dL, int Kw, int N) {
    int n = blockIdx.x * 256 + threadIdx.x;
    if (n >= N) return;
    int kw = blockIdx.y;
    size_t nw = (size_t)Kw * N;
    size_t bs = (size_t)blockIdx.z * 2u * nw;
    size_t bd = (size_t)blockIdx.z * nw;
    float a0 = src[bs + (size_t)(2 * kw) * N + n];
    float a1 = src[bs + (size_t)(2 * kw + 1) * N + n];
    uint32_t h, l;
    split_pack(a0, a1, h, l);
    dH[bd + (size_t)kw * N + n] = h;
    dL[bd + (size_t)kw * N + n] = l;
}

// rmsnorm; optional fp32 out; packed hi/lo words (row stride n/2)
__global__ void rmsnorm_pack_k(const float* __restrict__ in, const float* __restrict__ w,
                               float* __restrict__ outf,
                               uint32_t* __restrict__ pH, uint32_t* __restrict__ pL, int n) {
    int t = blockIdx.x;
    const float* r = in + (size_t)t * n;
    int tid = threadIdx.x;
    __shared__ float red[256];
    float s = 0.f;
    for (int i = tid; i < n; i += 256) { float vv = r[i]; s += vv * vv; }
    red[tid] = s; __syncthreads();
    for (int o = 128; o > 0; o >>= 1) { if (tid < o) red[tid] += red[tid + o]; __syncthreads(); }
    float rs = rsqrtf(red[0] / (float)n + EPSF);
    int nw = n >> 1;
    for (int i = tid; i < nw; i += 256) {
        float x0 = r[2 * i] * rs * w[2 * i];
        float x1 = r[2 * i + 1] * rs * w[2 * i + 1];
        if (outf) { outf[(size_t)t * n + 2 * i] = x0; outf[(size_t)t * n + 2 * i + 1] = x1; }
        uint32_t h, l;
        split_pack(x0, x1, h, l);
        pH[(size_t)t * nw + i] = h;
        pL[(size_t)t * nw + i] = l;
    }
}

// =======================================================================
// bf16x3 split-precision tensor-core GEMM, pre-packed operands.
// MT=2 -> BM=64, BN=128, BK=32; __launch_bounds__(256,2) for 2 CTAs/SM.
// SW swaps grid axes (m-fastest) for B-panel L2 reuse on huge-N GEMMs.
// =======================================================================
template <bool ADD, int MT, bool SW>
__global__ __launch_bounds__(256, 2) void tbgemm_k(
    const uint32_t* __restrict__ AHg, const uint32_t* __restrict__ ALg,
    const uint32_t* __restrict__ B0H, const uint32_t* __restrict__ B0L,
    const uint32_t* __restrict__ B1H, const uint32_t* __restrict__ B1L,
    const uint32_t* __restrict__ B2H, const uint32_t* __restrict__ B2L,
    float* __restrict__ C0, float* __restrict__ C1, float* __restrict__ C2,
    int M, int N, int Kd) {
    extern __shared__ uint32_t smw[];
    const int AW = MT * 512;
    const int BUF = AW * 2 + 4096;
    const int Kw = Kd >> 1;

    const uint32_t* BHg = (blockIdx.z == 0) ? B0H : (blockIdx.z == 1 ? B1H : B2H);
    const uint32_t* BLg = (blockIdx.z == 0) ? B0L : (blockIdx.z == 1 ? B1L : B2L);
    float*          C   = (blockIdx.z == 0) ? C0  : (blockIdx.z == 1 ? C1  : C2);

    const int bm = (SW ? blockIdx.x : blockIdx.y) * (MT * 32);
    const int bn = (SW ? blockIdx.y : blockIdx.x) * 128;
    const int tid = threadIdx.x;
    const int warp = tid >> 5, lane = tid & 31;
    const int warpM = warp >> 2;
    const int warpN = warp & 3;
    const int g = lane >> 2, t4 = lane & 3;

    float acc[MT][4][4];
#pragma unroll
    for (int i = 0; i < MT; i++)
#pragma unroll
        for (int j = 0; j < 4; j++)
#pragma unroll
            for (int r = 0; r < 4; r++) acc[i][j][r] = 0.f;

    uint2 sa_h[MT], sa_l[MT];
    uint4 sb_h[2], sb_l[2];

    auto LOAD = [&](int kt) {
#pragma unroll
        for (int i = 0; i < MT; i++) {
            int id = i * 256 + tid;
            int r = id >> 3, c4 = id & 7;
            size_t off = (size_t)(bm + r) * Kw + kt * 16 + c4 * 2;
            sa_h[i] = *reinterpret_cast<const uint2*>(AHg + off);
            sa_l[i] = *reinterpret_cast<const uint2*>(ALg + off);
        }
#pragma unroll
        for (int i = 0; i < 2; i++) {
            int id = i * 256 + tid;
            int kw = id >> 5, n4 = id & 31;
            size_t off = (size_t)(kt * 16 + kw) * N + bn + n4 * 4;
            sb_h[i] = *reinterpret_cast<const uint4*>(BHg + off);
            sb_l[i] = *reinterpret_cast<const uint4*>(BLg + off);
        }
    };

    auto STORE = [&](int buf) {
        uint32_t* AH = smw + buf * BUF;
        uint32_t* AL = AH + AW;
        uint32_t* BH = AH + 2 * AW;
        uint32_t* BL = BH + 2048;
#pragma unroll
        for (int i = 0; i < MT; i++) {
            int id = i * 256 + tid;
            int r = id >> 3, c4 = id & 7;
            int off = r * 16 + ((c4 * 2) ^ ((r & 7) * 2));
            *reinterpret_cast<uint2*>(AH + off) = sa_h[i];
            *reinterpret_cast<uint2*>(AL + off) = sa_l[i];
        }
#pragma unroll
        for (int i = 0; i < 2; i++) {
            int id = i * 256 + tid;
            int kw = id >> 5, n4 = id & 31;
            int off = kw * 128 + ((n4 * 4) ^ ((kw * 8) & 127));
            *reinterpret_cast<uint4*>(BH + off) = sb_h[i];
            *reinterpret_cast<uint4*>(BL + off) = sb_l[i];
        }
    };

    auto COMPUTE = [&](int buf) {
        uint32_t* AH = smw + buf * BUF;
        uint32_t* AL = AH + AW;
        uint32_t* BH = AH + 2 * AW;
        uint32_t* BL = BH + 2048;
#pragma unroll
        for (int ks = 0; ks < 2; ks++) {
            uint32_t ah[MT][4], al[MT][4];
#pragma unroll
            for (int mt = 0; mt < MT; mt++) {
                int r0 = warpM * (MT * 16) + mt * 16 + g;
                int r1 = r0 + 8;
                int ka = ks * 8 + t4, kb = ka + 4;
                int o0 = r0 * 16 + (ka ^ ((r0 & 7) * 2));
                int o1 = r1 * 16 + (ka ^ ((r1 & 7) * 2));
                int o2 = r0 * 16 + (kb ^ ((r0 & 7) * 2));
                int o3 = r1 * 16 + (kb ^ ((r1 & 7) * 2));
                ah[mt][0] = AH[o0]; ah[mt][1] = AH[o1]; ah[mt][2] = AH[o2]; ah[mt][3] = AH[o3];
                al[mt][0] = AL[o0]; al[mt][1] = AL[o1]; al[mt][2] = AL[o2]; al[mt][3] = AL[o3];
            }
            uint32_t bh[4][2], bl[4][2];
#pragma unroll
            for (int nt = 0; nt < 4; nt++) {
                int n = warpN * 32 + nt * 8 + g;
                int k0w = ks * 8 + t4, k1w = k0w + 4;
                int o0 = k0w * 128 + (n ^ ((k0w * 8) & 127));
                int o1 = k1w * 128 + (n ^ ((k1w * 8) & 127));
                bh[nt][0] = BH[o0]; bh[nt][1] = BH[o1];
                bl[nt][0] = BL[o0]; bl[nt][1] = BL[o1];
            }
#pragma unroll
            for (int mt = 0; mt < MT; mt++)
#pragma unroll
                for (int nt = 0; nt < 4; nt++) {
                    mma_bf16(acc[mt][nt], al[mt], bh[nt]);
                    mma_bf16(acc[mt][nt], ah[mt], bl[nt]);
                    mma_bf16(acc[mt][nt], ah[mt], bh[nt]);
                }
        }
    };

    const int ntiles = Kd / 32;
    LOAD(0);
    STORE(0);
    __syncthreads();
    for (int kt = 0; kt < ntiles; kt++) {
        if (kt + 1 < ntiles) LOAD(kt + 1);
        COMPUTE(kt & 1);
        if (kt + 1 < ntiles) STORE((kt + 1) & 1);
        __syncthreads();
    }

#pragma unroll
    for (int mt = 0; mt < MT; mt++) {
        int r0 = bm + warpM * (MT * 16) + mt * 16 + g;
#pragma unroll
        for (int nt = 0; nt < 4; nt++) {
            int c0 = bn + warpN * 32 + nt * 8 + 2 * t4;
            float* p0 = C + (size_t)r0 * N + c0;
            float* p1 = C + (size_t)(r0 + 8) * N + c0;
            if (ADD) {
                p0[0] += acc[mt][nt][0]; p0[1] += acc[mt][nt][1];
                p1[0] += acc[mt][nt][2]; p1[1] += acc[mt][nt][3];
            } else {
                p0[0] = acc[mt][nt][0]; p0[1] = acc[mt][nt][1];
                p1[0] = acc[mt][nt][2]; p1[1] = acc[mt][nt][3];
            }
        }
    }
}

// =======================================================================
// Fused post-QKV, one 768-thread block per timestep.
// conv(K=4)+SiLU for q,k,v (thread = channel d); l2norm per head (warp
// pairs); beta = sigmoid(x @ Wb[:,h]) with 2 warps per head.
// =======================================================================
__global__ __launch_bounds__(768) void postqkv_k(
    const float* __restrict__ t0, const float* __restrict__ t1, const float* __restrict__ t2,
    const float* __restrict__ cq, const float* __restrict__ ck, const float* __restrict__ cv,
    const float* __restrict__ x, const float* __restrict__ Wb,
    float* __restrict__ q, float* __restrict__ k, float* __restrict__ v,
    float* __restrict__ beta) {
    int t = blockIdx.x;
    int d = threadIdx.x;            // 0..767
    int h = d >> 6;
    int warp = d >> 5, lane = d & 31;
    __shared__ float sx[DD];
    __shared__ float redq[24], redk[24], redb[24];

    sx[d] = x[(size_t)t * DD + d];

    auto conv = [&](const float* src, const float* w) -> float {
        float acc = 0.f;
#pragma unroll
        for (int j = 0; j < KC; j++) {
            int tt = t - (KC - 1) + j;
            if (tt >= 0) acc += src[(size_t)tt * DD + d] * w[d * KC + j];
        }
        return acc / (1.f + expf(-acc));
    };
    float qv = conv(t0, cq);
    float kv = conv(t1, ck);
    float vv = conv(t2, cv);

    float sq = qv * qv, sk = kv * kv;
#pragma unroll
    for (int o = 16; o > 0; o >>= 1) {
        sq += __shfl_xor_sync(0xffffffffu, sq, o);
        sk += __shfl_xor_sync(0xffffffffu, sk, o);
    }
    if (lane == 0) { redq[warp] = sq; redk[warp] = sk; }
    __syncthreads();

    // beta partial dot: warp w handles head w>>1, half w&1 (384 elems each)
    {
        int h2 = warp >> 1, half = warp & 1;
        float sb = 0.f;
        for (int i = half * 384 + lane; i < half * 384 + 384; i += 32)
            sb += sx[i] * Wb[i * HH + h2];
#pragma unroll
        for (int o = 16; o > 0; o >>= 1) sb += __shfl_xor_sync(0xffffffffu, sb, o);
        if (lane == 0) redb[warp] = sb;
    }

    float rq = rsqrtf(redq[2 * h] + redq[2 * h + 1] + EPSF);
    float rk = rsqrtf(redk[2 * h] + redk[2 * h + 1] + EPSF);
    size_t gi = (size_t)t * DD + d;
    q[gi] = qv * rq;
    k[gi] = kv * rk;
    v[gi] = vv;
    __syncthreads();
    if (d < HH) beta[t * HH + d] = 1.f / (1.f + expf(-(redb[2 * d] + redb[2 * d + 1])));
}

// =======================================================================
// Chunked delta rule, phase 1 (parallel; WY form) — unchanged from round 7.
// =======================================================================
__global__ __launch_bounds__(256) void deltaprep_k(
    const float* __restrict__ q, const float* __restrict__ k,
    const float* __restrict__ v, const float* __restrict__ beta,
    float* __restrict__ Qe, float* __restrict__ Of,
    float* __restrict__ Pm, float* __restrict__ Rm) {
    extern __shared__ float sm[];
    float* sK = sm;
    float* sV = sK + 64 * PSTR;
    float* sQ = sV + 64 * PSTR;
    float* bA = sQ + 64 * PSTR;
    float* bT = bA + 64 * PSTR;
    float* bU = bT + 64 * PSTR;
    float* sb = bU + 64 * PSTR;
    const int c = blockIdx.x, h = blockIdx.y;
    const int tid = threadIdx.x;
    const int tr = (tid >> 4) * 4, tc = (tid & 15) * 4;

    for (int i = tid; i < 4096; i += 256) {
        int t = i >> 6, d = i & 63;
        size_t g = (size_t)(c * 64 + t) * DD + h * 64 + d;
        sK[t * PSTR + d] = k[g];
        sV[t * PSTR + d] = v[g];
        sQ[t * PSTR + d] = q[g];
    }
    if (tid < 64) sb[tid] = beta[(c * 64 + tid) * HH + h];
    __syncthreads();

    {
        float acc[4][4] = {};
        for (int m = 0; m < 64; m++) {
            float a[4], b[4];
#pragma unroll
            for (int i = 0; i < 4; i++) a[i] = sK[(tr + i) * PSTR + m];
#pragma unroll
            for (int j = 0; j < 4; j++) b[j] = sK[(tc + j) * PSTR + m];
#pragma unroll
            for (int i = 0; i < 4; i++)
#pragma unroll
                for (int j = 0; j < 4; j++) acc[i][j] += a[i] * b[j];
        }
#pragma unroll
        for (int i = 0; i < 4; i++)
#pragma unroll
            for (int j = 0; j < 4; j++) {
                int t = tr + i, s = tc + j;
                bA[t * PSTR + s] = (s < t) ? acc[i][j] * sb[t] : 0.f;
            }
    }
    __syncthreads();

    for (int t = 0; t < 64; t++) {
        if (tid < 64) {
            float acc = (t == tid) ? 1.f : 0.f;
            for (int s = 0; s < t; s++) acc -= bA[t * PSTR + s] * bT[s * PSTR + tid];
            bT[t * PSTR + tid] = acc;
        }
        __syncthreads();
    }

    {
        float accW[4][4] = {}, accU[4][4] = {};
        for (int m = 0; m < 64; m++) {
            float a[4];
#pragma unroll
            for (int i = 0; i < 4; i++) a[i] = bT[(tr + i) * PSTR + m] * sb[m];
            float bk[4], bv[4];
#pragma unroll
            for (int j = 0; j < 4; j++) {
                bk[j] = sK[m * PSTR + tc + j];
                bv[j] = sV[m * PSTR + tc + j];
            }
#pragma unroll
            for (int i = 0; i < 4; i++)
#pragma unroll
                for (int j = 0; j < 4; j++) {
                    accW[i][j] += a[i] * bk[j];
                    accU[i][j] += a[i] * bv[j];
                }
        }
        __syncthreads();
#pragma unroll
        for (int i = 0; i < 4; i++)
#pragma unroll
            for (int j = 0; j < 4; j++) {
                bA[(tr + i) * PSTR + tc + j] = accW[i][j];
                bU[(tr + i) * PSTR + tc + j] = accU[i][j];
            }
    }
    __syncthreads();

    {
        float acc[4][4] = {};
        for (int m = 0; m < 64; m++) {
            float a[4], b[4];
#pragma unroll
            for (int i = 0; i < 4; i++) a[i] = sQ[(tr + i) * PSTR + m];
#pragma unroll
            for (int j = 0; j < 4; j++) b[j] = sK[(tc + j) * PSTR + m];
#pragma unroll
            for (int i = 0; i < 4; i++)
#pragma unroll
                for (int j = 0; j < 4; j++) acc[i][j] += a[i] * b[j];
        }
        __syncthreads();
#pragma unroll
        for (int i = 0; i < 4; i++)
#pragma unroll
            for (int j = 0; j < 4; j++) {
                int t = tr + i, s = tc + j;
                bT[t * PSTR + s] = (s <= t) ? acc[i][j] : 0.f;
            }
    }
    __syncthreads();

    const size_t base = ((size_t)(h * NCH + c)) << 12;

    {
        float accQ[4][4] = {}, accO[4][4] = {};
        for (int m = 0; m < 64; m++) {
            float a[4];
#pragma unroll
            for (int i = 0; i < 4; i++) a[i] = bT[(tr + i) * PSTR + m];
            float bw[4], bu[4];
#pragma unroll
            for (int j = 0; j < 4; j++) {
                bw[j] = bA[m * PSTR + tc + j];
                bu[j] = bU[m * PSTR + tc + j];
            }
#pragma unroll
            for (int i = 0; i < 4; i++)
#pragma unroll
                for (int j = 0; j < 4; j++) {
                    accQ[i][j] += a[i] * bw[j];
                    accO[i][j] += a[i] * bu[j];
                }
        }
#pragma unroll
        for (int i = 0; i < 4; i++)
#pragma unroll
            for (int j = 0; j < 4; j++) {
                Qe[base + (tr + i) * 64 + tc + j] =
                    sQ[(tr + i) * PSTR + tc + j] - accQ[i][j];
                Of[base + (tr + i) * 64 + tc + j] = accO[i][j];
            }
    }

    {
        float accP[4][4] = {}, accR[4][4] = {};
        for (int m = 0; m < 64; m++) {
            float a[4];
#pragma unroll
            for (int i = 0; i < 4; i++) a[i] = sK[m * PSTR + tr + i];
            float bw[4], bu[4];
#pragma unroll
            for (int j = 0; j < 4; j++) {
                bw[j] = bA[m * PSTR + tc + j];
                bu[j] = bU[m * PSTR + tc + j];
            }
#pragma unroll
            for (int i = 0; i < 4; i++)
#pragma unroll
                for (int j = 0; j < 4; j++) {
                    accP[i][j] += a[i] * bw[j];
                    accR[i][j] += a[i] * bu[j];
                }
        }
#pragma unroll
        for (int i = 0; i < 4; i++)
#pragma unroll
            for (int j = 0; j < 4; j++) {
                Pm[base + (tr + i) * 64 + tc + j] = accP[i][j];
                Rm[base + (tr + i) * 64 + tc + j] = accR[i][j];
            }
    }
}

// Chunked delta rule, phase 2 (scan) — unchanged from round 7.
__global__ __launch_bounds__(256) void deltascan_k(
    const float* __restrict__ Qe, const float* __restrict__ Of,
    const float* __restrict__ Pm, const float* __restrict__ Rm,
    float* __restrict__ o) {
    const int h = blockIdx.x, cg = blockIdx.y;
    const int tid = threadIdx.x;
    __shared__ float sQe[64 * PSTR], sP[64 * PSTR];
    __shared__ float S[64 * 9], sOf[512], sR[512];

    for (int i = tid; i < 64 * 9; i += 256) S[i] = 0.f;
    __syncthreads();

#pragma unroll 1
    for (int c = 0; c < NCH; c++) {
        size_t base = ((size_t)(h * NCH + c)) << 12;
        for (int i = tid; i < 4096; i += 256) {
            int t = i >> 6, d = i & 63;
            sQe[t * PSTR + d] = Qe[base + i];
            sP[t * PSTR + d] = Pm[base + i];
        }
        for (int i = tid; i < 512; i += 256) {
            int t = i >> 3, j = i & 7;
            sOf[i] = Of[base + t * 64 + cg * 8 + j];
            sR[i] = Rm[base + t * 64 + cg * 8 + j];
        }
        __syncthreads();

        float outv[2], ns[2];
#pragma unroll
        for (int u = 0; u < 2; u++) {
            int idx = tid + u * 256;
            int t = idx >> 3, j = idx & 7;
            float a1 = sOf[idx];
            float a2 = S[t * 9 + j] + sR[idx];
#pragma unroll
            for (int m = 0; m < 64; m++) {
                float sv = S[m * 9 + j];
                a1 += sQe[t * PSTR + m] * sv;
                a2 -= sP[t * PSTR + m] * sv;
            }
            outv[u] = a1;
            ns[u] = a2;
        }
#pragma unroll
        for (int u = 0; u < 2; u++) {
            int idx = tid + u * 256;
            int t = idx >> 3, j = idx & 7;
            o[(size_t)(c * 64 + t) * DD + h * 64 + cg * 8 + j] = outv[u];
        }
        __syncthreads();
#pragma unroll
        for (int u = 0; u < 2; u++) {
            int idx = tid + u * 256;
            int t = idx >> 3, j = idx & 7;
            S[t * 9 + j] = ns[u];
        }
        __syncthreads();
    }
}

// per-64 rmsnorm * w of delta output -> packed words (feeds Wo GEMM)
__global__ void headnorm_pack_k(const float* __restrict__ o, const float* __restrict__ w,
                                uint32_t* __restrict__ pH, uint32_t* __restrict__ pL) {
    int gw = (blockIdx.x * blockDim.x + threadIdx.x) >> 5;
    int lane = threadIdx.x & 31;
    if (gw >= TT * HH) return;
    const float* r = o + (size_t)gw * 64;
    float a = r[2 * lane], b = r[2 * lane + 1];
    float s = a * a + b * b;
#pragma unroll
    for (int os = 16; os > 0; os >>= 1) s += __shfl_xor_sync(0xffffffffu, s, os);
    float rs = rsqrtf(s * (1.f / 64.f) + EPSF);
    int t = gw / HH, h = gw % HH;
    uint32_t hw, lw;
    split_pack(a * rs * w[2 * lane], b * rs * w[2 * lane + 1], hw, lw);
    size_t wi = (size_t)t * 384 + h * 32 + lane;
    pH[wi] = hw;
    pL[wi] = lw;
}

// silu(g)*u, writes packed words; i indexes element pairs
__global__ void silu_mul_pack_k(const float* __restrict__ g, const float* __restrict__ u,
                                uint32_t* __restrict__ pH, uint32_t* __restrict__ pL) {
    int i = blockIdx.x * blockDim.x + threadIdx.x;
    if (i >= TT * FFF / 2) return;
    float g0 = g[2 * i], g1 = g[2 * i + 1];
    float y0 = (g0 / (1.f + expf(-g0))) * u[2 * i];
    float y1 = (g1 / (1.f + expf(-g1))) * u[2 * i + 1];
    uint32_t h, l;
    split_pack(y0, y1, h, l);
    pH[i] = h;
    pL[i] = l;
}

// online-softmax cross-entropy row pass (single read of logits)
__global__ void loss_rows_k(const float* __restrict__ logits, const int* __restrict__ tgt,
                            float* __restrict__ nll, float* __restrict__ msk) {
    int t = blockIdx.x;
    const float* r = logits + (size_t)t * VV;
    int tid = threadIdx.x;
    __shared__ float sm_m[256], sm_s[256];
    float m = -INFINITY, s = 0.f;
    for (int i = tid; i < VV; i += 256) {
        float v = r[i];
        if (v > m) { s = s * expf(m - v) + 1.f; m = v; }
        else s += expf(v - m);
    }
    sm_m[tid] = m; sm_s[tid] = s;
    __syncthreads();
    for (int o = 128; o > 0; o >>= 1) {
        if (tid < o) {
            float m1 = sm_m[tid], m2 = sm_m[tid + o];
            float M = fmaxf(m1, m2);
            sm_s[tid] = sm_s[tid] * expf(m1 - M) + sm_s[tid + o] * expf(m2 - M);
            sm_m[tid] = M;
        }
        __syncthreads();
    }
    if (tid == 0) {
        float rowmax = sm_m[0], denom = sm_s[0];
        int tg = tgt[t];
        float mask = (tg >= 0) ? 1.f : 0.f;
        int tc = tg < 0 ? 0 : (tg > VV - 1 ? VV - 1 : tg);
        float lp = r[tc] - rowmax - logf(denom);
        nll[t] = -lp * mask;
        msk[t] = mask;
    }
}

__global__ void loss_reduce_k(const float* __restrict__ nll, const float* __restrict__ msk,
                              float* __restrict__ out) {
    int tid = threadIdx.x;
    __shared__ float r1[256], r2[256];
    float s = 0.f, c = 0.f;
    for (int i = tid; i < TT; i += 256) { s += nll[i]; c += msk[i]; }
    r1[tid] = s; r2[tid] = c; __syncthreads();
    for (int o = 128; o > 0; o >>= 1) {
        if (tid < o) { r1[tid] += r1[tid + o]; r2[tid] += r2[tid + o]; }
        __syncthreads();
    }
    if (tid == 0) out[0] = r1[0] / fmaxf(r2[0], 1.f);
}

// ---------------- host launcher ----------------
extern "C" void kernel_launch(void* const* d_in, const int* in_sizes, int n_in,
                              void* d_out, int out_size) {
    const int*   idx   = (const int*)d_in[0];
    const int*   tgt   = (const int*)d_in[1];
    const float* emb   = (const float*)d_in[2];
    const float* Wq    = (const float*)d_in[3];
    const float* Wk    = (const float*)d_in[4];
    const float* Wv    = (const float*)d_in[5];
    const float* convq = (const float*)d_in[6];
    const float* convk = (const float*)d_in[7];
    const float* convv = (const float*)d_in[8];
    const float* Wb    = (const float*)d_in[9];
    const float* onw   = (const float*)d_in[10];
    const float* Wo    = (const float*)d_in[11];
    const float* anw   = (const float*)d_in[12];
    const float* mnw   = (const float*)d_in[13];
    const float* Wg    = (const float*)d_in[14];
    const float* Wu    = (const float*)d_in[15];
    const float* Wd    = (const float*)d_in[16];
    const float* fnw   = (const float*)d_in[17];
    const float* lmh   = (const float*)d_in[18];
    float* out = (float*)d_out;

    float *hb, *xb, *t0, *t1, *t2, *qb, *kb, *vb, *ob, *bb, *gb, *ub, *nl, *mk, *lfb;
    cudaGetSymbolAddress((void**)&hb,  g_h);
    cudaGetSymbolAddress((void**)&xb,  g_x);
    cudaGetSymbolAddress((void**)&t0,  g_t0);
    cudaGetSymbolAddress((void**)&t1,  g_t1);
    cudaGetSymbolAddress((void**)&t2,  g_t2);
    cudaGetSymbolAddress((void**)&qb,  g_q);
    cudaGetSymbolAddress((void**)&kb,  g_k);
    cudaGetSymbolAddress((void**)&vb,  g_v);
    cudaGetSymbolAddress((void**)&ob,  g_o);
    cudaGetSymbolAddress((void**)&bb,  g_beta);
    cudaGetSymbolAddress((void**)&gb,  g_gate);
    cudaGetSymbolAddress((void**)&ub,  g_up);
    cudaGetSymbolAddress((void**)&nl,  g_nll);
    cudaGetSymbolAddress((void**)&mk,  g_msk);
    cudaGetSymbolAddress((void**)&lfb, g_logits_fb);

    float *dQe, *dOf, *dPm, *dRm;
    cudaGetSymbolAddress((void**)&dQe, g_Qe);
    cudaGetSymbolAddress((void**)&dOf, g_Of);
    cudaGetSymbolAddress((void**)&dPm, g_Pm);
    cudaGetSymbolAddress((void**)&dRm, g_Rm);

    uint32_t *pAh, *pAl;
    uint32_t *wqh, *wql, *wkh, *wkl, *wvh, *wvl, *woh, *wol;
    uint32_t *wgh, *wgl, *wuh, *wul, *wdh, *wdl, *lmH, *lmL;
    cudaGetSymbolAddress((void**)&pAh, g_pA_h);
    cudaGetSymbolAddress((void**)&pAl, g_pA_l);
    cudaGetSymbolAddress((void**)&wqh, g_Wq_h); cudaGetSymbolAddress((void**)&wql, g_Wq_l);
    cudaGetSymbolAddress((void**)&wkh, g_Wk_h); cudaGetSymbolAddress((void**)&wkl, g_Wk_l);
    cudaGetSymbolAddress((void**)&wvh, g_Wv_h); cudaGetSymbolAddress((void**)&wvl, g_Wv_l);
    cudaGetSymbolAddress((void**)&woh, g_Wo_h); cudaGetSymbolAddress((void**)&wol, g_Wo_l);
    cudaGetSymbolAddress((void**)&wgh, g_Wg_h); cudaGetSymbolAddress((void**)&wgl, g_Wg_l);
    cudaGetSymbolAddress((void**)&wuh, g_Wu_h); cudaGetSymbolAddress((void**)&wul, g_Wu_l);
    cudaGetSymbolAddress((void**)&wdh, g_Wd_h); cudaGetSymbolAddress((void**)&wdl, g_Wd_l);
    cudaGetSymbolAddress((void**)&lmH, g_Lm_h); cudaGetSymbolAddress((void**)&lmL, g_Lm_l);

    const int SMEMB = (2 * 1024 + 4096) * 2 * 4;  // 49152 (MT=2, double-buffered)
    const int PREPSM = (6 * 64 * PSTR + 64) * 4 + 256;
    cudaFuncSetAttribute((const void*)tbgemm_k<false, 2, false>, cudaFuncAttributeMaxDynamicSharedMemorySize, SMEMB);
    cudaFuncSetAttribute((const void*)tbgemm_k<true, 2, false>,  cudaFuncAttributeMaxDynamicSharedMemorySize, SMEMB);
    cudaFuncSetAttribute((const void*)tbgemm_k<false, 2, true>,  cudaFuncAttributeMaxDynamicSharedMemorySize, SMEMB);
    cudaFuncSetAttribute((const void*)deltaprep_k, cudaFuncAttributeMaxDynamicSharedMemorySize, PREPSM);

    // ---- pack all weights (div-free grids) ----
    pack_w_k<<<dim3(3, 384, LL), 256>>>(Wq, wqh, wql, 384, DD);
    pack_w_k<<<dim3(3, 384, LL), 256>>>(Wk, wkh, wkl, 384, DD);
    pack_w_k<<<dim3(3, 384, LL), 256>>>(Wv, wvh, wvl, 384, DD);
    pack_w_k<<<dim3(3, 384, LL), 256>>>(Wo, woh, wol, 384, DD);
    pack_w_k<<<dim3(8, 384, LL), 256>>>(Wg, wgh, wgl, 384, FFF);
    pack_w_k<<<dim3(8, 384, LL), 256>>>(Wu, wuh, wul, 384, FFF);
    pack_w_k<<<dim3(3, 1024, LL), 256>>>(Wd, wdh, wdl, 1024, DD);
    pack_w_k<<<dim3((VV + 255) / 256, 384, 1), 256>>>(lmh, lmH, lmL, 384, VV);

    const int ewarpBlocks = (TT * HH * 32 + 255) / 256;
    const int ffwBlocks = (TT * FFF / 2 + 255) / 256;

    embed_k<<<TT, 256>>>(idx, emb, hb);

    for (int l = 0; l < LL; l++) {
        const float* cq_l = convq + (size_t)l * DD * KC;
        const float* ck_l = convk + (size_t)l * DD * KC;
        const float* cv_l = convv + (size_t)l * DD * KC;
        const float* Wb_l = Wb + (size_t)l * DD * HH;
        const float* on_l = onw + (size_t)l * DKK;
        const float* an_l = anw + (size_t)l * DD;
        const float* mn_l = mnw + (size_t)l * DD;

        rmsnorm_pack_k<<<TT, 256>>>(hb, an_l, xb, pAh, pAl, DD);

        dim3 gQKV(DD / 128, TT / 64, 3);
        tbgemm_k<false, 2, false><<<gQKV, 256, SMEMB>>>(
            pAh, pAl,
            wqh + (size_t)l * WSM, wql + (size_t)l * WSM,
            wkh + (size_t)l * WSM, wkl + (size_t)l * WSM,
            wvh + (size_t)l * WSM, wvl + (size_t)l * WSM,
            t0, t1, t2, TT, DD, DD);

        postqkv_k<<<TT, 768>>>(t0, t1, t2, cq_l, ck_l, cv_l, xb, Wb_l, qb, kb, vb, bb);

        deltaprep_k<<<dim3(NCH, HH), 256, PREPSM>>>(qb, kb, vb, bb, dQe, dOf, dPm, dRm);
        deltascan_k<<<dim3(HH, 8), 256>>>(dQe, dOf, dPm, dRm, ob);

        headnorm_pack_k<<<ewarpBlocks, 256>>>(ob, on_l, pAh, pAl);

        dim3 gD(DD / 128, TT / 64, 1);
        tbgemm_k<true, 2, false><<<gD, 256, SMEMB>>>(
            pAh, pAl,
            woh + (size_t)l * WSM, wol + (size_t)l * WSM,
            woh + (size_t)l * WSM, wol + (size_t)l * WSM,
            woh + (size_t)l * WSM, wol + (size_t)l * WSM,
            hb, hb, hb, TT, DD, DD);

        rmsnorm_pack_k<<<TT, 256>>>(hb, mn_l, nullptr, pAh, pAl, DD);

        dim3 gGU(FFF / 128, TT / 64, 2);
        tbgemm_k<false, 2, false><<<gGU, 256, SMEMB>>>(
            pAh, pAl,
            wgh + (size_t)l * WGU, wgl + (size_t)l * WGU,
            wuh + (size_t)l * WGU, wul + (size_t)l * WGU,
            wuh + (size_t)l * WGU, wul + (size_t)l * WGU,
            gb, ub, ub, TT, FFF, DD);

        silu_mul_pack_k<<<ffwBlocks, 256>>>(gb, ub, pAh, pAl);

        tbgemm_k<true, 2, false><<<gD, 256, SMEMB>>>(
            pAh, pAl,
            wdh + (size_t)l * WDN, wdl + (size_t)l * WDN,
            wdh + (size_t)l * WDN, wdl + (size_t)l * WDN,
            wdh + (size_t)l * WDN, wdl + (size_t)l * WDN,
            hb, hb, hb, TT, DD, FFF);
    }

    rmsnorm_pack_k<<<TT, 256>>>(hb, fnw, nullptr, pAh, pAl, DD);

    const size_t LOGN = (size_t)TT * VV;
    float* logits = ((size_t)out_size >= LOGN) ? out : lfb;
    // LM head: m-fastest grid so each B panel is read from DRAM once
    dim3 gV(TT / 64, VV / 128, 1);
    tbgemm_k<false, 2, true><<<gV, 256, SMEMB>>>(pAh, pAl, lmH, lmL, lmH, lmL, lmH, lmL,
                                                 logits, logits, logits, TT, VV, DD);

    loss_rows_k<<<TT, 256>>>(logits, tgt, nl, mk);
    float* loss_dst = nullptr;
    if ((size_t)out_size >= LOGN + 1) loss_dst = out + LOGN;
    else if ((size_t)out_size < LOGN) loss_dst = out;
    if (loss_dst) loss_reduce_k<<<1, 256>>>(nl, mk, loss_dst);
}